// round 4
// baseline (speedup 1.0000x reference)
#include <cuda_runtime.h>
#include <math.h>

// Problem constants
#define B_  2
#define L_  2048
#define D_  2048
#define H_  16
#define DH  128
#define BL  (B_ * L_)          // 4096
#define NEG (-1.0e9f)

// ---------------------------------------------------------------------------
// Scratch (device globals; no runtime allocation allowed)
// ---------------------------------------------------------------------------
__device__ float g_qkv[(size_t)BL * 3 * D_];       // 25.2M floats
__device__ float g_q[(size_t)B_ * H_ * L_ * DH];   // 8.4M
__device__ float g_k[(size_t)B_ * H_ * L_ * DH];
__device__ float g_v[(size_t)B_ * H_ * L_ * DH];
__device__ float g_y[(size_t)BL * D_];             // attention output, (B,L,D)
__device__ float g_cos[L_ * 64];
__device__ float g_sin[L_ * 64];

// ---------------------------------------------------------------------------
// K0: RoPE tables.  freq computed as fp32 product (matches reference), then
// sin/cos in double for accurate argument reduction at pos up to 2047.
// ---------------------------------------------------------------------------
__global__ void rope_tables_kernel() {
    int idx = blockIdx.x * blockDim.x + threadIdx.x;
    if (idx >= L_ * 64) return;
    int l = idx >> 6;
    int i = idx & 63;
    float invf = (float)exp(-((double)i / 64.0) * log(10000.0));
    float arg  = (float)l * invf;                 // fp32 multiply like reference
    g_cos[idx] = (float)cos((double)arg);
    g_sin[idx] = (float)sin((double)arg);
}

// ---------------------------------------------------------------------------
// K1/K4: fp32 SGEMM, C[M,N] = A[M,K] * B[K,N], all row-major.
// 128x128 block tile, BK=16, 256 threads, 8x8 register micro-tile.
// M,N multiples of 128; K multiple of 16 (true for all our shapes).
// ---------------------------------------------------------------------------
__global__ __launch_bounds__(256)
void sgemm128_kernel(const float* __restrict__ A, const float* __restrict__ Bm,
                     float* __restrict__ C, int M, int N, int K) {
    __shared__ float As[16][128];   // transposed: As[k][m]
    __shared__ float Bs[16][128];   // Bs[k][n]

    const int tid = threadIdx.x;
    const int tx  = tid & 15;
    const int ty  = tid >> 4;
    const int m0  = blockIdx.y * 128;
    const int n0  = blockIdx.x * 128;

    const float* Ab = A  + (size_t)m0 * K;
    const float* Bb = Bm + n0;

    float acc[8][8];
#pragma unroll
    for (int i = 0; i < 8; i++)
#pragma unroll
        for (int j = 0; j < 8; j++) acc[i][j] = 0.0f;

    for (int k0 = 0; k0 < K; k0 += 16) {
        // Load A tile (128x16) transposed into As
#pragma unroll
        for (int it = 0; it < 2; it++) {
            int idx = tid + it * 256;        // over 512 float4s
            int row = idx >> 2;
            int c4  = idx & 3;
            float4 v = *(const float4*)(Ab + (size_t)row * K + k0 + c4 * 4);
            As[c4 * 4 + 0][row] = v.x;
            As[c4 * 4 + 1][row] = v.y;
            As[c4 * 4 + 2][row] = v.z;
            As[c4 * 4 + 3][row] = v.w;
        }
        // Load B tile (16x128)
#pragma unroll
        for (int it = 0; it < 2; it++) {
            int idx = tid + it * 256;
            int row = idx >> 5;
            int c4  = idx & 31;
            *(float4*)(&Bs[row][c4 * 4]) =
                *(const float4*)(Bb + (size_t)(k0 + row) * N + c4 * 4);
        }
        __syncthreads();

#pragma unroll
        for (int k = 0; k < 16; k++) {
            float ra[8], rb[8];
            *(float4*)(ra)     = *(const float4*)(&As[k][ty * 8]);
            *(float4*)(ra + 4) = *(const float4*)(&As[k][ty * 8 + 4]);
            *(float4*)(rb)     = *(const float4*)(&Bs[k][tx * 8]);
            *(float4*)(rb + 4) = *(const float4*)(&Bs[k][tx * 8 + 4]);
#pragma unroll
            for (int i = 0; i < 8; i++)
#pragma unroll
                for (int j = 0; j < 8; j++)
                    acc[i][j] += ra[i] * rb[j];
        }
        __syncthreads();
    }

    // Write back (vectorized)
    float* Cb = C + (size_t)(m0 + ty * 8) * N + n0 + tx * 8;
#pragma unroll
    for (int i = 0; i < 8; i++) {
        *(float4*)(Cb + (size_t)i * N)     = make_float4(acc[i][0], acc[i][1], acc[i][2], acc[i][3]);
        *(float4*)(Cb + (size_t)i * N + 4) = make_float4(acc[i][4], acc[i][5], acc[i][6], acc[i][7]);
    }
}

// ---------------------------------------------------------------------------
// K2: split qkv, apply RoPE to q,k, scatter into (B,H,L,Dh) layout.
// One block per (b,l) row.
// ---------------------------------------------------------------------------
__global__ __launch_bounds__(256)
void rope_split_kernel() {
    const int row = blockIdx.x;          // b*L + l
    const int b = row / L_;
    const int l = row - b * L_;
    const float* src = g_qkv + (size_t)row * 3 * D_;

    for (int d = threadIdx.x; d < D_; d += blockDim.x) {
        int h  = d >> 7;
        int dd = d & 127;
        int fi = dd & 63;
        float c = g_cos[l * 64 + fi];
        float s = g_sin[l * 64 + fi];
        size_t dst = (((size_t)(b * H_ + h)) * L_ + l) * DH + dd;

        float qv   = src[d];
        float qrot = (dd < 64) ? -src[d + 64] : src[d - 64];
        g_q[dst] = qv * c + qrot * s;

        float kv   = src[D_ + d];
        float krot = (dd < 64) ? -src[D_ + d + 64] : src[D_ + d - 64];
        g_k[dst] = kv * c + krot * s;

        g_v[dst] = src[2 * D_ + d];
    }
}

// ---------------------------------------------------------------------------
// K3: causal flash attention.  One block per (q-tile of 128, b*H).
// smem: Qs [d][qi] 128x128, KPs (K^T then P^T) stride 132, Vs [kk][d] 128x128.
// 256 threads, 8x8 register micro-tiles for both GEMMs, online softmax.
// ---------------------------------------------------------------------------
#define KP_STRIDE 132
#define SMEM_FLASH_BYTES ((16384 + 128 * KP_STRIDE + 16384) * 4 + 128 * 4)

__global__ __launch_bounds__(256)
void flash_attn_kernel(const int* __restrict__ amask) {
    extern __shared__ float sm[];
    float* Qs  = sm;                              // 128*128
    float* KPs = sm + 16384;                      // 128*KP_STRIDE
    float* Vs  = KPs + 128 * KP_STRIDE;           // 128*128
    int*   msk = (int*)(Vs + 16384);              // 128 ints

    const int tid = threadIdx.x;
    const int tx  = tid & 15;
    const int ty  = tid >> 4;
    const int qt  = blockIdx.x;
    const int bh  = blockIdx.y;
    const int b   = bh >> 4;
    const int h   = bh & 15;
    const int q0  = qt * 128;

    const float* Qg = g_q + ((size_t)bh * L_ + q0) * DH;
    const float* Kg = g_k + (size_t)bh * L_ * DH;
    const float* Vg = g_v + (size_t)bh * L_ * DH;

    // Load Q tile transposed: Qs[d][qi]
#pragma unroll
    for (int it = 0; it < 16; it++) {
        int idx = tid + it * 256;        // 4096 float4s
        int r   = idx >> 5;              // q row 0..127
        int c4  = idx & 31;              // d/4
        float4 v = *(const float4*)(Qg + (size_t)r * DH + c4 * 4);
        Qs[(c4 * 4 + 0) * 128 + r] = v.x;
        Qs[(c4 * 4 + 1) * 128 + r] = v.y;
        Qs[(c4 * 4 + 2) * 128 + r] = v.z;
        Qs[(c4 * 4 + 3) * 128 + r] = v.w;
    }

    float m[8], lsum[8], acc[8][8];
#pragma unroll
    for (int i = 0; i < 8; i++) {
        m[i] = -INFINITY;
        lsum[i] = 0.0f;
#pragma unroll
        for (int j = 0; j < 8; j++) acc[i][j] = 0.0f;
    }

    const float scale = 0.088388347648318447f;    // 1/sqrt(128)

    for (int kt = 0; kt <= qt; kt++) {
        const int k0 = kt * 128;
        __syncthreads();   // previous iter done reading KPs/Vs; Q stores visible (iter 0)

        // Load K tile transposed (KPs[d][kj], stride KP_STRIDE) and V tile (Vs[kk][d])
#pragma unroll
        for (int it = 0; it < 16; it++) {
            int idx = tid + it * 256;
            int r   = idx >> 5;
            int c4  = idx & 31;
            float4 kv = *(const float4*)(Kg + (size_t)(k0 + r) * DH + c4 * 4);
            KPs[(c4 * 4 + 0) * KP_STRIDE + r] = kv.x;
            KPs[(c4 * 4 + 1) * KP_STRIDE + r] = kv.y;
            KPs[(c4 * 4 + 2) * KP_STRIDE + r] = kv.z;
            KPs[(c4 * 4 + 3) * KP_STRIDE + r] = kv.w;
            *(float4*)(&Vs[r * 128 + c4 * 4]) =
                *(const float4*)(Vg + (size_t)(k0 + r) * DH + c4 * 4);
        }
        if (tid < 128) msk[tid] = amask[b * L_ + k0 + tid];
        __syncthreads();

        // S = Q * K^T  (128x128x128)
        float s[8][8];
#pragma unroll
        for (int i = 0; i < 8; i++)
#pragma unroll
            for (int j = 0; j < 8; j++) s[i][j] = 0.0f;

#pragma unroll 4
        for (int kk = 0; kk < 128; kk++) {
            float ra[8], rb[8];
            *(float4*)(ra)     = *(const float4*)(&Qs[kk * 128 + ty * 8]);
            *(float4*)(ra + 4) = *(const float4*)(&Qs[kk * 128 + ty * 8 + 4]);
            *(float4*)(rb)     = *(const float4*)(&KPs[kk * KP_STRIDE + tx * 8]);
            *(float4*)(rb + 4) = *(const float4*)(&KPs[kk * KP_STRIDE + tx * 8 + 4]);
#pragma unroll
            for (int i = 0; i < 8; i++)
#pragma unroll
                for (int j = 0; j < 8; j++)
                    s[i][j] += ra[i] * rb[j];
        }

        // Scale + causal + pad mask
        const bool diag = (kt == qt);
#pragma unroll
        for (int i = 0; i < 8; i++) {
            int qi = q0 + ty * 8 + i;
#pragma unroll
            for (int j = 0; j < 8; j++) {
                int kj = k0 + tx * 8 + j;
                float v = s[i][j] * scale;
                if ((diag && kj > qi) || (msk[tx * 8 + j] == 0)) v = NEG;
                s[i][j] = v;
            }
        }

        // Online softmax update (rows span 16 lanes sharing ty)
#pragma unroll
        for (int i = 0; i < 8; i++) {
            float mx = s[i][0];
#pragma unroll
            for (int j = 1; j < 8; j++) mx = fmaxf(mx, s[i][j]);
#pragma unroll
            for (int o = 8; o > 0; o >>= 1)
                mx = fmaxf(mx, __shfl_xor_sync(0xffffffffu, mx, o));
            float mn  = fmaxf(m[i], mx);
            float fac = __expf(m[i] - mn);
            m[i] = mn;
            float rs = 0.0f;
#pragma unroll
            for (int j = 0; j < 8; j++) {
                s[i][j] = __expf(s[i][j] - mn);
                rs += s[i][j];
            }
#pragma unroll
            for (int o = 8; o > 0; o >>= 1)
                rs += __shfl_xor_sync(0xffffffffu, rs, o);
            lsum[i] = lsum[i] * fac + rs;
#pragma unroll
            for (int j = 0; j < 8; j++) acc[i][j] *= fac;
        }

        __syncthreads();   // done reading KPs as K

        // Write P transposed: KPs[kj][qi]
#pragma unroll
        for (int j = 0; j < 8; j++) {
            *(float4*)(&KPs[(tx * 8 + j) * KP_STRIDE + ty * 8]) =
                make_float4(s[0][j], s[1][j], s[2][j], s[3][j]);
            *(float4*)(&KPs[(tx * 8 + j) * KP_STRIDE + ty * 8 + 4]) =
                make_float4(s[4][j], s[5][j], s[6][j], s[7][j]);
        }
        __syncthreads();

        // acc += P * V   (128x128x128); thread covers (qi = ty*8.., d = tx*8..)
#pragma unroll 4
        for (int kk = 0; kk < 128; kk++) {
            float ra[8], rb[8];
            *(float4*)(ra)     = *(const float4*)(&KPs[kk * KP_STRIDE + ty * 8]);
            *(float4*)(ra + 4) = *(const float4*)(&KPs[kk * KP_STRIDE + ty * 8 + 4]);
            *(float4*)(rb)     = *(const float4*)(&Vs[kk * 128 + tx * 8]);
            *(float4*)(rb + 4) = *(const float4*)(&Vs[kk * 128 + tx * 8 + 4]);
#pragma unroll
            for (int i = 0; i < 8; i++)
#pragma unroll
                for (int j = 0; j < 8; j++)
                    acc[i][j] += ra[i] * rb[j];
        }
    }

    // Epilogue: normalize and write to (B,L,D) layout
#pragma unroll
    for (int i = 0; i < 8; i++) {
        float inv = 1.0f / lsum[i];
        int qi = q0 + ty * 8 + i;
        float* out = g_y + (size_t)(b * L_ + qi) * D_ + h * DH + tx * 8;
        *(float4*)(out)     = make_float4(acc[i][0] * inv, acc[i][1] * inv,
                                          acc[i][2] * inv, acc[i][3] * inv);
        *(float4*)(out + 4) = make_float4(acc[i][4] * inv, acc[i][5] * inv,
                                          acc[i][6] * inv, acc[i][7] * inv);
    }
}

// ---------------------------------------------------------------------------
// Launcher
// ---------------------------------------------------------------------------
extern "C" void kernel_launch(void* const* d_in, const int* in_sizes, int n_in,
                              void* d_out, int out_size) {
    const float* x     = nullptr;
    const int*   am    = nullptr;
    const float* wqkv  = nullptr;
    const float* wproj = nullptr;

    for (int i = 0; i < n_in; i++) {
        switch (in_sizes[i]) {
            case BL * D_:      x     = (const float*)d_in[i]; break;   // 8388608
            case BL:           am    = (const int*)d_in[i];   break;   // 4096
            case D_ * 3 * D_:  wqkv  = (const float*)d_in[i]; break;   // 12582912
            case D_ * D_:      wproj = (const float*)d_in[i]; break;   // 4194304
            default: break;
        }
    }
    // Positional fallback (metadata order: x, attention_mask, w_qkv, w_proj)
    if (!x)     x     = (const float*)d_in[0];
    if (!am)    am    = (const int*)d_in[1];
    if (!wqkv)  wqkv  = (const float*)d_in[2];
    if (!wproj) wproj = (const float*)d_in[3];

    float* qkv_p; cudaGetSymbolAddress((void**)&qkv_p, g_qkv);
    float* y_p;   cudaGetSymbolAddress((void**)&y_p,   g_y);

    cudaFuncSetAttribute(flash_attn_kernel,
                         cudaFuncAttributeMaxDynamicSharedMemorySize,
                         SMEM_FLASH_BYTES);

    // K0: RoPE tables
    rope_tables_kernel<<<(L_ * 64 + 255) / 256, 256>>>();

    // K1: qkv = x @ w_qkv   (4096 x 6144 x 2048)
    sgemm128_kernel<<<dim3(3 * D_ / 128, BL / 128), 256>>>(x, wqkv, qkv_p,
                                                           BL, 3 * D_, D_);

    // K2: RoPE + split into (B,H,L,Dh)
    rope_split_kernel<<<BL, 256>>>();

    // K3: causal flash attention -> g_y (B,L,D)
    flash_attn_kernel<<<dim3(L_ / 128, B_ * H_), 256, SMEM_FLASH_BYTES>>>(am);

    // K4: out = y @ w_proj   (4096 x 2048 x 2048)
    sgemm128_kernel<<<dim3(D_ / 128, BL / 128), 256>>>(y_p, wproj, (float*)d_out,
                                                       BL, D_, D_);
}

// round 6
// speedup vs baseline: 1.8051x; 1.8051x over previous
#include <cuda_runtime.h>
#include <math.h>

// Problem constants
#define B_  2
#define L_  2048
#define D_  2048
#define H_  16
#define DH  128
#define BL  (B_ * L_)          // 4096
#define NEG (-1.0e9f)

// ---------------------------------------------------------------------------
// Scratch (device globals; no runtime allocation allowed)
// ---------------------------------------------------------------------------
__device__ float g_qkv[(size_t)BL * 3 * D_];       // 25.2M floats
__device__ float g_q[(size_t)B_ * H_ * L_ * DH];   // 8.4M
__device__ float g_k[(size_t)B_ * H_ * L_ * DH];
__device__ float g_v[(size_t)B_ * H_ * L_ * DH];
__device__ float g_y[(size_t)BL * D_];             // attention output, (B,L,D)
__device__ float g_cos[L_ * 64];
__device__ float g_sin[L_ * 64];

// ---------------------------------------------------------------------------
// K0: RoPE tables.
// ---------------------------------------------------------------------------
__global__ void rope_tables_kernel() {
    int idx = blockIdx.x * blockDim.x + threadIdx.x;
    if (idx >= L_ * 64) return;
    int l = idx >> 6;
    int i = idx & 63;
    float invf = (float)exp(-((double)i / 64.0) * log(10000.0));
    float arg  = (float)l * invf;                 // fp32 multiply like reference
    g_cos[idx] = (float)cos((double)arg);
    g_sin[idx] = (float)sin((double)arg);
}

// ---------------------------------------------------------------------------
// tf32 helpers
// ---------------------------------------------------------------------------
__device__ __forceinline__ unsigned f2tf32(float x) {
    unsigned r;
    asm("cvt.rna.tf32.f32 %0, %1;" : "=r"(r) : "f"(x));
    return r;
}

__device__ __forceinline__ void mma_tf32(float (&d)[4], const unsigned (&a)[4],
                                         const unsigned (&b)[2]) {
    asm volatile(
        "mma.sync.aligned.m16n8k8.row.col.f32.tf32.tf32.f32 "
        "{%0,%1,%2,%3}, {%4,%5,%6,%7}, {%8,%9}, {%0,%1,%2,%3};\n"
        : "+f"(d[0]), "+f"(d[1]), "+f"(d[2]), "+f"(d[3])
        : "r"(a[0]), "r"(a[1]), "r"(a[2]), "r"(a[3]), "r"(b[0]), "r"(b[1]));
}

// ---------------------------------------------------------------------------
// K1/K4: tf32 tensor-core GEMM, C[M,N] = A[M,K]*B[K,N], row-major.
// 128x128 block tile, BK=32, 256 threads (8 warps, 2x4), 64x32 warp tile.
// Smem stride 136 => conflict-free fragment LDS; XOR swizzle on A columns
// => conflict-free transposing STS.
// M,N multiples of 128; K multiple of 32.
// ---------------------------------------------------------------------------
__global__ __launch_bounds__(256)
void sgemm_tf32_kernel(const float* __restrict__ A, const float* __restrict__ Bm,
                       float* __restrict__ C, int M, int N, int K) {
    __shared__ unsigned As[32 * 136];   // As[k][m^swz], swz = ((k>>2)&7)<<2
    __shared__ unsigned Bs[32 * 136];   // Bs[k][n]

    const int tid  = threadIdx.x;
    const int lane = tid & 31;
    const int w    = tid >> 5;
    const int gid  = lane >> 2;         // 0..7
    const int tig  = lane & 3;          // 0..3
    const int wm   = (w >> 2) * 64;     // warp M offset
    const int wn   = (w & 3) * 32;      // warp N offset
    const int m0   = blockIdx.y * 128;
    const int n0   = blockIdx.x * 128;

    float acc[4][4][4];
#pragma unroll
    for (int mt = 0; mt < 4; mt++)
#pragma unroll
        for (int nt = 0; nt < 4; nt++)
#pragma unroll
            for (int i = 0; i < 4; i++) acc[mt][nt][i] = 0.0f;

    for (int k0 = 0; k0 < K; k0 += 32) {
        // ---- Load + convert tiles into smem ----
#pragma unroll
        for (int it = 0; it < 4; it++) {
            int fid = tid + it * 256;
            {   // A tile: 128 rows x 32 k, transposed into As[k][m]
                int r  = fid >> 3;          // m row 0..127
                int c4 = fid & 7;           // k/4
                float4 v = *(const float4*)(A + (size_t)(m0 + r) * K + k0 + c4 * 4);
                int pc   = r ^ (c4 << 2);   // swizzled column
                int base = (c4 * 4) * 136 + pc;
                As[base]       = f2tf32(v.x);
                As[base + 136] = f2tf32(v.y);
                As[base + 272] = f2tf32(v.z);
                As[base + 408] = f2tf32(v.w);
            }
            {   // B tile: 32 k-rows x 128 n
                int r  = fid >> 5;          // k row 0..31
                int c4 = fid & 31;          // n/4
                float4 v = *(const float4*)(Bm + (size_t)(k0 + r) * N + n0 + c4 * 4);
                unsigned* dst = &Bs[r * 136 + c4 * 4];
                dst[0] = f2tf32(v.x);
                dst[1] = f2tf32(v.y);
                dst[2] = f2tf32(v.z);
                dst[3] = f2tf32(v.w);
            }
        }
        __syncthreads();

        // ---- 4 k-steps of m16n8k8 ----
#pragma unroll
        for (int kk = 0; kk < 32; kk += 8) {
            const int s0 = ((kk >> 2) & 7) << 2;
            const int s1 = (((kk >> 2) + 1) & 7) << 2;
            unsigned af[4][4], bf[4][2];
#pragma unroll
            for (int mt = 0; mt < 4; mt++) {
                int mb = wm + mt * 16 + gid;
                af[mt][0] = As[(kk + tig) * 136 + (mb ^ s0)];
                af[mt][1] = As[(kk + tig) * 136 + ((mb + 8) ^ s0)];
                af[mt][2] = As[(kk + tig + 4) * 136 + (mb ^ s1)];
                af[mt][3] = As[(kk + tig + 4) * 136 + ((mb + 8) ^ s1)];
            }
#pragma unroll
            for (int nt = 0; nt < 4; nt++) {
                int nb = wn + nt * 8 + gid;
                bf[nt][0] = Bs[(kk + tig) * 136 + nb];
                bf[nt][1] = Bs[(kk + tig + 4) * 136 + nb];
            }
#pragma unroll
            for (int mt = 0; mt < 4; mt++)
#pragma unroll
                for (int nt = 0; nt < 4; nt++)
                    mma_tf32(acc[mt][nt], af[mt], bf[nt]);
        }
        __syncthreads();
    }

    // ---- Epilogue ----
#pragma unroll
    for (int mt = 0; mt < 4; mt++) {
#pragma unroll
        for (int nt = 0; nt < 4; nt++) {
            int r = m0 + wm + mt * 16 + gid;
            int c = n0 + wn + nt * 8 + tig * 2;
            float* p0 = C + (size_t)r * N + c;
            *(float2*)p0 = make_float2(acc[mt][nt][0], acc[mt][nt][1]);
            float* p1 = p0 + (size_t)8 * N;
            *(float2*)p1 = make_float2(acc[mt][nt][2], acc[mt][nt][3]);
        }
    }
}

// ---------------------------------------------------------------------------
// K2: split qkv, apply RoPE to q,k, scatter into (B,H,L,Dh) layout.
// ---------------------------------------------------------------------------
__global__ __launch_bounds__(256)
void rope_split_kernel() {
    const int row = blockIdx.x;          // b*L + l
    const int b = row / L_;
    const int l = row - b * L_;
    const float* src = g_qkv + (size_t)row * 3 * D_;

    for (int d = threadIdx.x; d < D_; d += blockDim.x) {
        int h  = d >> 7;
        int dd = d & 127;
        int fi = dd & 63;
        float c = g_cos[l * 64 + fi];
        float s = g_sin[l * 64 + fi];
        size_t dst = (((size_t)(b * H_ + h)) * L_ + l) * DH + dd;

        float qv   = src[d];
        float qrot = (dd < 64) ? -src[d + 64] : src[d - 64];
        g_q[dst] = qv * c + qrot * s;

        float kv   = src[D_ + d];
        float krot = (dd < 64) ? -src[D_ + d + 64] : src[D_ + d - 64];
        g_k[dst] = kv * c + krot * s;

        g_v[dst] = src[2 * D_ + d];
    }
}

// ---------------------------------------------------------------------------
// K3: causal flash attention (fp32 FFMA path — unchanged from passing R4).
// ---------------------------------------------------------------------------
#define KP_STRIDE 132
#define SMEM_FLASH_BYTES ((16384 + 128 * KP_STRIDE + 16384) * 4 + 128 * 4)

__global__ __launch_bounds__(256)
void flash_attn_kernel(const int* __restrict__ amask) {
    extern __shared__ float sm[];
    float* Qs  = sm;                              // 128*128
    float* KPs = sm + 16384;                      // 128*KP_STRIDE
    float* Vs  = KPs + 128 * KP_STRIDE;           // 128*128
    int*   msk = (int*)(Vs + 16384);              // 128 ints

    const int tid = threadIdx.x;
    const int tx  = tid & 15;
    const int ty  = tid >> 4;
    const int qt  = blockIdx.x;
    const int bh  = blockIdx.y;
    const int b   = bh >> 4;
    const int h   = bh & 15;
    const int q0  = qt * 128;

    const float* Qg = g_q + ((size_t)bh * L_ + q0) * DH;
    const float* Kg = g_k + (size_t)bh * L_ * DH;
    const float* Vg = g_v + (size_t)bh * L_ * DH;

#pragma unroll
    for (int it = 0; it < 16; it++) {
        int idx = tid + it * 256;
        int r   = idx >> 5;
        int c4  = idx & 31;
        float4 v = *(const float4*)(Qg + (size_t)r * DH + c4 * 4);
        Qs[(c4 * 4 + 0) * 128 + r] = v.x;
        Qs[(c4 * 4 + 1) * 128 + r] = v.y;
        Qs[(c4 * 4 + 2) * 128 + r] = v.z;
        Qs[(c4 * 4 + 3) * 128 + r] = v.w;
    }

    float m[8], lsum[8], acc[8][8];
#pragma unroll
    for (int i = 0; i < 8; i++) {
        m[i] = -INFINITY;
        lsum[i] = 0.0f;
#pragma unroll
        for (int j = 0; j < 8; j++) acc[i][j] = 0.0f;
    }

    const float scale = 0.088388347648318447f;    // 1/sqrt(128)

    for (int kt = 0; kt <= qt; kt++) {
        const int k0 = kt * 128;
        __syncthreads();

#pragma unroll
        for (int it = 0; it < 16; it++) {
            int idx = tid + it * 256;
            int r   = idx >> 5;
            int c4  = idx & 31;
            float4 kv = *(const float4*)(Kg + (size_t)(k0 + r) * DH + c4 * 4);
            KPs[(c4 * 4 + 0) * KP_STRIDE + r] = kv.x;
            KPs[(c4 * 4 + 1) * KP_STRIDE + r] = kv.y;
            KPs[(c4 * 4 + 2) * KP_STRIDE + r] = kv.z;
            KPs[(c4 * 4 + 3) * KP_STRIDE + r] = kv.w;
            *(float4*)(&Vs[r * 128 + c4 * 4]) =
                *(const float4*)(Vg + (size_t)(k0 + r) * DH + c4 * 4);
        }
        if (tid < 128) msk[tid] = amask[b * L_ + k0 + tid];
        __syncthreads();

        float s[8][8];
#pragma unroll
        for (int i = 0; i < 8; i++)
#pragma unroll
            for (int j = 0; j < 8; j++) s[i][j] = 0.0f;

#pragma unroll 4
        for (int kk = 0; kk < 128; kk++) {
            float ra[8], rb[8];
            *(float4*)(ra)     = *(const float4*)(&Qs[kk * 128 + ty * 8]);
            *(float4*)(ra + 4) = *(const float4*)(&Qs[kk * 128 + ty * 8 + 4]);
            *(float4*)(rb)     = *(const float4*)(&KPs[kk * KP_STRIDE + tx * 8]);
            *(float4*)(rb + 4) = *(const float4*)(&KPs[kk * KP_STRIDE + tx * 8 + 4]);
#pragma unroll
            for (int i = 0; i < 8; i++)
#pragma unroll
                for (int j = 0; j < 8; j++)
                    s[i][j] += ra[i] * rb[j];
        }

        const bool diag = (kt == qt);
#pragma unroll
        for (int i = 0; i < 8; i++) {
            int qi = q0 + ty * 8 + i;
#pragma unroll
            for (int j = 0; j < 8; j++) {
                int kj = k0 + tx * 8 + j;
                float v = s[i][j] * scale;
                if ((diag && kj > qi) || (msk[tx * 8 + j] == 0)) v = NEG;
                s[i][j] = v;
            }
        }

#pragma unroll
        for (int i = 0; i < 8; i++) {
            float mx = s[i][0];
#pragma unroll
            for (int j = 1; j < 8; j++) mx = fmaxf(mx, s[i][j]);
#pragma unroll
            for (int o = 8; o > 0; o >>= 1)
                mx = fmaxf(mx, __shfl_xor_sync(0xffffffffu, mx, o));
            float mn  = fmaxf(m[i], mx);
            float fac = __expf(m[i] - mn);
            m[i] = mn;
            float rs = 0.0f;
#pragma unroll
            for (int j = 0; j < 8; j++) {
                s[i][j] = __expf(s[i][j] - mn);
                rs += s[i][j];
            }
#pragma unroll
            for (int o = 8; o > 0; o >>= 1)
                rs += __shfl_xor_sync(0xffffffffu, rs, o);
            lsum[i] = lsum[i] * fac + rs;
#pragma unroll
            for (int j = 0; j < 8; j++) acc[i][j] *= fac;
        }

        __syncthreads();

#pragma unroll
        for (int j = 0; j < 8; j++) {
            *(float4*)(&KPs[(tx * 8 + j) * KP_STRIDE + ty * 8]) =
                make_float4(s[0][j], s[1][j], s[2][j], s[3][j]);
            *(float4*)(&KPs[(tx * 8 + j) * KP_STRIDE + ty * 8 + 4]) =
                make_float4(s[4][j], s[5][j], s[6][j], s[7][j]);
        }
        __syncthreads();

#pragma unroll 4
        for (int kk = 0; kk < 128; kk++) {
            float ra[8], rb[8];
            *(float4*)(ra)     = *(const float4*)(&KPs[kk * KP_STRIDE + ty * 8]);
            *(float4*)(ra + 4) = *(const float4*)(&KPs[kk * KP_STRIDE + ty * 8 + 4]);
            *(float4*)(rb)     = *(const float4*)(&Vs[kk * 128 + tx * 8]);
            *(float4*)(rb + 4) = *(const float4*)(&Vs[kk * 128 + tx * 8 + 4]);
#pragma unroll
            for (int i = 0; i < 8; i++)
#pragma unroll
                for (int j = 0; j < 8; j++)
                    acc[i][j] += ra[i] * rb[j];
        }
    }

#pragma unroll
    for (int i = 0; i < 8; i++) {
        float inv = 1.0f / lsum[i];
        int qi = q0 + ty * 8 + i;
        float* out = g_y + (size_t)(b * L_ + qi) * D_ + h * DH + tx * 8;
        *(float4*)(out)     = make_float4(acc[i][0] * inv, acc[i][1] * inv,
                                          acc[i][2] * inv, acc[i][3] * inv);
        *(float4*)(out + 4) = make_float4(acc[i][4] * inv, acc[i][5] * inv,
                                          acc[i][6] * inv, acc[i][7] * inv);
    }
}

// ---------------------------------------------------------------------------
// Launcher
// ---------------------------------------------------------------------------
extern "C" void kernel_launch(void* const* d_in, const int* in_sizes, int n_in,
                              void* d_out, int out_size) {
    const float* x     = nullptr;
    const int*   am    = nullptr;
    const float* wqkv  = nullptr;
    const float* wproj = nullptr;

    for (int i = 0; i < n_in; i++) {
        switch (in_sizes[i]) {
            case BL * D_:      x     = (const float*)d_in[i]; break;
            case BL:           am    = (const int*)d_in[i];   break;
            case D_ * 3 * D_:  wqkv  = (const float*)d_in[i]; break;
            case D_ * D_:      wproj = (const float*)d_in[i]; break;
            default: break;
        }
    }
    if (!x)     x     = (const float*)d_in[0];
    if (!am)    am    = (const int*)d_in[1];
    if (!wqkv)  wqkv  = (const float*)d_in[2];
    if (!wproj) wproj = (const float*)d_in[3];

    float* qkv_p; cudaGetSymbolAddress((void**)&qkv_p, g_qkv);
    float* y_p;   cudaGetSymbolAddress((void**)&y_p,   g_y);

    cudaFuncSetAttribute(flash_attn_kernel,
                         cudaFuncAttributeMaxDynamicSharedMemorySize,
                         SMEM_FLASH_BYTES);

    // K0: RoPE tables
    rope_tables_kernel<<<(L_ * 64 + 255) / 256, 256>>>();

    // K1: qkv = x @ w_qkv   (4096 x 6144 x 2048)  — tf32 tensor cores
    sgemm_tf32_kernel<<<dim3(3 * D_ / 128, BL / 128), 256>>>(x, wqkv, qkv_p,
                                                             BL, 3 * D_, D_);

    // K2: RoPE + split into (B,H,L,Dh)
    rope_split_kernel<<<BL, 256>>>();

    // K3: causal flash attention -> g_y (B,L,D)
    flash_attn_kernel<<<dim3(L_ / 128, B_ * H_), 256, SMEM_FLASH_BYTES>>>(am);

    // K4: out = y @ w_proj   (4096 x 2048 x 2048) — tf32 tensor cores
    sgemm_tf32_kernel<<<dim3(D_ / 128, BL / 128), 256>>>(y_p, wproj, (float*)d_out,
                                                         BL, D_, D_);
}

// round 8
// speedup vs baseline: 2.6286x; 1.4562x over previous
#include <cuda_runtime.h>
#include <math.h>

// Problem constants
#define B_  2
#define L_  2048
#define D_  2048
#define H_  16
#define DH  128
#define BL  (B_ * L_)          // 4096
#define NEG (-1.0e9f)

// ---------------------------------------------------------------------------
// Scratch (device globals; no runtime allocation allowed)
// ---------------------------------------------------------------------------
__device__ float g_qkv[(size_t)BL * 3 * D_];
__device__ float g_q[(size_t)B_ * H_ * L_ * DH];
__device__ float g_k[(size_t)B_ * H_ * L_ * DH];
__device__ float g_v[(size_t)B_ * H_ * L_ * DH];
__device__ float g_y[(size_t)BL * D_];
__device__ float g_cos[L_ * 64];
__device__ float g_sin[L_ * 64];

// ---------------------------------------------------------------------------
// K0: RoPE tables.
// ---------------------------------------------------------------------------
__global__ void rope_tables_kernel() {
    int idx = blockIdx.x * blockDim.x + threadIdx.x;
    if (idx >= L_ * 64) return;
    int l = idx >> 6;
    int i = idx & 63;
    float invf = (float)exp(-((double)i / 64.0) * log(10000.0));
    float arg  = (float)l * invf;                 // fp32 multiply like reference
    g_cos[idx] = (float)cos((double)arg);
    g_sin[idx] = (float)sin((double)arg);
}

// ---------------------------------------------------------------------------
// tf32 helpers
// ---------------------------------------------------------------------------
__device__ __forceinline__ unsigned f2tf32(float x) {
    unsigned r;
    asm("cvt.rna.tf32.f32 %0, %1;" : "=r"(r) : "f"(x));
    return r;
}

__device__ __forceinline__ void mma_tf32(float (&d)[4], const unsigned (&a)[4],
                                         unsigned b0, unsigned b1) {
    asm volatile(
        "mma.sync.aligned.m16n8k8.row.col.f32.tf32.tf32.f32 "
        "{%0,%1,%2,%3}, {%4,%5,%6,%7}, {%8,%9}, {%0,%1,%2,%3};\n"
        : "+f"(d[0]), "+f"(d[1]), "+f"(d[2]), "+f"(d[3])
        : "r"(a[0]), "r"(a[1]), "r"(a[2]), "r"(a[3]), "r"(b0), "r"(b1));
}

// ---------------------------------------------------------------------------
// K1/K4: tf32 GEMM with register prefetch pipelining.
// C[M,N] = A[M,K]*B[K,N], row-major. 128x128 tile, BK=32, 256 thr, 2x4 warps.
// ---------------------------------------------------------------------------
__device__ __forceinline__ void gemm_ldg_tile(
    const float* __restrict__ A, const float* __restrict__ Bm,
    int K, int N, int m0, int n0, int k0, int tid,
    float4 (&pa)[4], float4 (&pb)[4]) {
#pragma unroll
    for (int it = 0; it < 4; it++) {
        int fid = tid + it * 256;
        pa[it] = *(const float4*)(A + (size_t)(m0 + (fid >> 3)) * K + k0 + (fid & 7) * 4);
        pb[it] = *(const float4*)(Bm + (size_t)(k0 + (fid >> 5)) * N + n0 + (fid & 31) * 4);
    }
}

__device__ __forceinline__ void gemm_sts_tile(
    unsigned* As, unsigned* Bs, int tid,
    const float4 (&pa)[4], const float4 (&pb)[4]) {
#pragma unroll
    for (int it = 0; it < 4; it++) {
        int fid = tid + it * 256;
        {
            int r  = fid >> 3;
            int c4 = fid & 7;
            int pc   = r ^ (c4 << 2);
            int base = (c4 * 4) * 136 + pc;
            As[base]       = f2tf32(pa[it].x);
            As[base + 136] = f2tf32(pa[it].y);
            As[base + 272] = f2tf32(pa[it].z);
            As[base + 408] = f2tf32(pa[it].w);
        }
        {
            int r  = fid >> 5;
            int c4 = fid & 31;
            unsigned* dst = &Bs[r * 136 + c4 * 4];
            dst[0] = f2tf32(pb[it].x);
            dst[1] = f2tf32(pb[it].y);
            dst[2] = f2tf32(pb[it].z);
            dst[3] = f2tf32(pb[it].w);
        }
    }
}

__global__ __launch_bounds__(256)
void sgemm_tf32_kernel(const float* __restrict__ A, const float* __restrict__ Bm,
                       float* __restrict__ C, int M, int N, int K) {
    __shared__ unsigned As[32 * 136];
    __shared__ unsigned Bs[32 * 136];

    const int tid  = threadIdx.x;
    const int lane = tid & 31;
    const int w    = tid >> 5;
    const int gid  = lane >> 2;
    const int tig  = lane & 3;
    const int wm   = (w >> 2) * 64;
    const int wn   = (w & 3) * 32;
    const int m0   = blockIdx.y * 128;
    const int n0   = blockIdx.x * 128;

    float acc[4][4][4];
#pragma unroll
    for (int mt = 0; mt < 4; mt++)
#pragma unroll
        for (int nt = 0; nt < 4; nt++)
#pragma unroll
            for (int i = 0; i < 4; i++) acc[mt][nt][i] = 0.0f;

    // Preload tile 0
    {
        float4 pa[4], pb[4];
        gemm_ldg_tile(A, Bm, K, N, m0, n0, 0, tid, pa, pb);
        gemm_sts_tile(As, Bs, tid, pa, pb);
    }
    __syncthreads();

    for (int k0 = 0; k0 < K; k0 += 32) {
        // Prefetch next tile into registers (overlaps with MMA below)
        float4 pa[4], pb[4];
        const bool has_next = (k0 + 32) < K;
        if (has_next)
            gemm_ldg_tile(A, Bm, K, N, m0, n0, k0 + 32, tid, pa, pb);

#pragma unroll
        for (int kk = 0; kk < 32; kk += 8) {
            const int s0 = ((kk >> 2) & 7) << 2;
            const int s1 = (((kk >> 2) + 1) & 7) << 2;
            unsigned af[4][4], bf[4][2];
#pragma unroll
            for (int mt = 0; mt < 4; mt++) {
                int mb = wm + mt * 16 + gid;
                af[mt][0] = As[(kk + tig) * 136 + (mb ^ s0)];
                af[mt][1] = As[(kk + tig) * 136 + ((mb + 8) ^ s0)];
                af[mt][2] = As[(kk + tig + 4) * 136 + (mb ^ s1)];
                af[mt][3] = As[(kk + tig + 4) * 136 + ((mb + 8) ^ s1)];
            }
#pragma unroll
            for (int nt = 0; nt < 4; nt++) {
                int nb = wn + nt * 8 + gid;
                bf[nt][0] = Bs[(kk + tig) * 136 + nb];
                bf[nt][1] = Bs[(kk + tig + 4) * 136 + nb];
            }
#pragma unroll
            for (int mt = 0; mt < 4; mt++)
#pragma unroll
                for (int nt = 0; nt < 4; nt++)
                    mma_tf32(acc[mt][nt], af[mt], bf[nt][0], bf[nt][1]);
        }

        if (has_next) {
            __syncthreads();
            gemm_sts_tile(As, Bs, tid, pa, pb);
            __syncthreads();
        }
    }

    // Epilogue
#pragma unroll
    for (int mt = 0; mt < 4; mt++) {
#pragma unroll
        for (int nt = 0; nt < 4; nt++) {
            int r = m0 + wm + mt * 16 + gid;
            int c = n0 + wn + nt * 8 + tig * 2;
            float* p0 = C + (size_t)r * N + c;
            *(float2*)p0 = make_float2(acc[mt][nt][0], acc[mt][nt][1]);
            float* p1 = p0 + (size_t)8 * N;
            *(float2*)p1 = make_float2(acc[mt][nt][2], acc[mt][nt][3]);
        }
    }
}

// ---------------------------------------------------------------------------
// K2: split qkv, apply RoPE to q,k, scatter into (B,H,L,Dh) layout.
// ---------------------------------------------------------------------------
__global__ __launch_bounds__(256)
void rope_split_kernel() {
    const int row = blockIdx.x;
    const int b = row / L_;
    const int l = row - b * L_;
    const float* src = g_qkv + (size_t)row * 3 * D_;

    for (int d = threadIdx.x; d < D_; d += blockDim.x) {
        int h  = d >> 7;
        int dd = d & 127;
        int fi = dd & 63;
        float c = g_cos[l * 64 + fi];
        float s = g_sin[l * 64 + fi];
        size_t dst = (((size_t)(b * H_ + h)) * L_ + l) * DH + dd;

        float qv   = src[d];
        float qrot = (dd < 64) ? -src[d + 64] : src[d - 64];
        g_q[dst] = qv * c + qrot * s;

        float kv   = src[D_ + d];
        float krot = (dd < 64) ? -src[D_ + d + 64] : src[D_ + d - 64];
        g_k[dst] = kv * c + krot * s;

        g_v[dst] = src[2 * D_ + d];
    }
}

// ---------------------------------------------------------------------------
// K3: causal flash attention on tf32 tensor cores.
// 256 threads, 8 warps. Warp w owns q rows [w*16, w*16+16) -- full 128 k cols,
// so softmax is warp-local. P stays in registers (fragment reshaped by quad
// shuffles). Smem: Qs/Vs tf32 bits stride 136; Ks transposed with 5-bit XOR
// swizzle (col' = r ^ (d>>2)): conflict-free STS and fragment LDS.
// ---------------------------------------------------------------------------
#define FL_STRIDE 136
#define SMEM_FLASH_BYTES (3 * 128 * FL_STRIDE * 4 + 512)

__global__ __launch_bounds__(256)
void flash_tf32_kernel(const int* __restrict__ amask) {
    extern __shared__ unsigned smu[];
    unsigned* Qs = smu;                          // [q][d]   tf32 bits
    unsigned* Ks = smu + 128 * FL_STRIDE;        // [d][k^swz] tf32 bits
    unsigned* Vs = smu + 2 * 128 * FL_STRIDE;    // [k][d]   tf32 bits
    int* msk = (int*)(smu + 3 * 128 * FL_STRIDE);

    const int tid  = threadIdx.x;
    const int lane = tid & 31;
    const int w    = tid >> 5;
    const int gid  = lane >> 2;
    const int tig  = lane & 3;
    const int qt   = (int)gridDim.x - 1 - blockIdx.x;  // heavy tiles first
    const int bh   = blockIdx.y;
    const int b    = bh >> 4;
    const int h    = bh & 15;
    const int q0   = qt * 128;
    const int wq   = w * 16;

    const float* Qg = g_q + ((size_t)bh * L_ + q0) * DH;
    const float* Kg = g_k + (size_t)bh * L_ * DH;
    const float* Vg = g_v + (size_t)bh * L_ * DH;

    // Load Q tile -> tf32 bits, [q][d] stride 136
#pragma unroll
    for (int it = 0; it < 16; it++) {
        int idx = tid + it * 256;
        int r   = idx >> 5;
        int c4  = idx & 31;
        float4 v = *(const float4*)(Qg + (size_t)r * DH + c4 * 4);
        uint4 u = make_uint4(f2tf32(v.x), f2tf32(v.y), f2tf32(v.z), f2tf32(v.w));
        *(uint4*)(&Qs[r * FL_STRIDE + c4 * 4]) = u;
    }

    float oacc[16][4];
    float mprev[2], lsum[2];
#pragma unroll
    for (int dt = 0; dt < 16; dt++)
#pragma unroll
        for (int e = 0; e < 4; e++) oacc[dt][e] = 0.0f;
    mprev[0] = mprev[1] = -INFINITY;
    lsum[0] = lsum[1] = 0.0f;

    const float scale = 0.088388347648318447f;   // 1/sqrt(128)
    const int rowa0 = (wq + gid) * FL_STRIDE;
    const int rowa1 = rowa0 + 8 * FL_STRIDE;

    for (int kt = 0; kt <= qt; kt++) {
        const int k0 = kt * 128;
        __syncthreads();   // prev iter done reading Ks/Vs (and Qs visible, it 0)

        // Load K (transposed + swizzled) and V tiles as tf32 bits
#pragma unroll
        for (int it = 0; it < 16; it++) {
            int idx = tid + it * 256;
            int r   = idx >> 5;               // k index within tile
            int c4  = idx & 31;               // d/4
            float4 kv = *(const float4*)(Kg + (size_t)(k0 + r) * DH + c4 * 4);
            int d0 = c4 * 4;
            Ks[(d0 + 0) * FL_STRIDE + (r ^ ((d0 + 0) >> 2))] = f2tf32(kv.x);
            Ks[(d0 + 1) * FL_STRIDE + (r ^ ((d0 + 1) >> 2))] = f2tf32(kv.y);
            Ks[(d0 + 2) * FL_STRIDE + (r ^ ((d0 + 2) >> 2))] = f2tf32(kv.z);
            Ks[(d0 + 3) * FL_STRIDE + (r ^ ((d0 + 3) >> 2))] = f2tf32(kv.w);
            float4 vv = *(const float4*)(Vg + (size_t)(k0 + r) * DH + c4 * 4);
            uint4 u = make_uint4(f2tf32(vv.x), f2tf32(vv.y), f2tf32(vv.z), f2tf32(vv.w));
            *(uint4*)(&Vs[r * FL_STRIDE + c4 * 4]) = u;
        }
        if (tid < 128) msk[tid] = amask[b * L_ + k0 + tid];
        __syncthreads();

        // ---- S = Q K^T (warp: 16 q-rows x 128 k-cols) ----
        float sacc[16][4];
#pragma unroll
        for (int nt = 0; nt < 16; nt++)
#pragma unroll
            for (int e = 0; e < 4; e++) sacc[nt][e] = 0.0f;

#pragma unroll
        for (int kk = 0; kk < 128; kk += 8) {
            unsigned a[4];
            a[0] = Qs[rowa0 + kk + tig];
            a[1] = Qs[rowa1 + kk + tig];
            a[2] = Qs[rowa0 + kk + tig + 4];
            a[3] = Qs[rowa1 + kk + tig + 4];
            const int d0 = kk + tig, d1 = d0 + 4;
            const unsigned* K0 = Ks + d0 * FL_STRIDE;
            const unsigned* K1 = Ks + d1 * FL_STRIDE;
            const int sw0 = d0 >> 2, sw1 = d1 >> 2;
#pragma unroll
            for (int nt = 0; nt < 16; nt++) {
                int kc = nt * 8 + gid;
                mma_tf32(sacc[nt], a, K0[kc ^ sw0], K1[kc ^ sw1]);
            }
        }

        // ---- scale + mask ----
        const bool diag = (kt == qt);
        const int qi0 = q0 + wq + gid;
        const int qi1 = qi0 + 8;
#pragma unroll
        for (int nt = 0; nt < 16; nt++) {
            int kjb = nt * 8 + 2 * tig;
#pragma unroll
            for (int e = 0; e < 4; e++) {
                int kj = kjb + (e & 1);
                int qi = (e < 2) ? qi0 : qi1;
                float v = sacc[nt][e] * scale;
                if ((diag && (k0 + kj) > qi) || (msk[kj] == 0)) v = NEG;
                sacc[nt][e] = v;
            }
        }

        // ---- online softmax (rows warp-local; reduce across quad lanes) ----
        float mx0 = -INFINITY, mx1 = -INFINITY;
#pragma unroll
        for (int nt = 0; nt < 16; nt++) {
            mx0 = fmaxf(mx0, fmaxf(sacc[nt][0], sacc[nt][1]));
            mx1 = fmaxf(mx1, fmaxf(sacc[nt][2], sacc[nt][3]));
        }
        mx0 = fmaxf(mx0, __shfl_xor_sync(0xffffffffu, mx0, 1));
        mx0 = fmaxf(mx0, __shfl_xor_sync(0xffffffffu, mx0, 2));
        mx1 = fmaxf(mx1, __shfl_xor_sync(0xffffffffu, mx1, 1));
        mx1 = fmaxf(mx1, __shfl_xor_sync(0xffffffffu, mx1, 2));

        float mn0 = fmaxf(mprev[0], mx0);
        float mn1 = fmaxf(mprev[1], mx1);
        float fac0 = __expf(mprev[0] - mn0);
        float fac1 = __expf(mprev[1] - mn1);
        mprev[0] = mn0; mprev[1] = mn1;

        float rs0 = 0.0f, rs1 = 0.0f;
#pragma unroll
        for (int nt = 0; nt < 16; nt++) {
            sacc[nt][0] = __expf(sacc[nt][0] - mn0); rs0 += sacc[nt][0];
            sacc[nt][1] = __expf(sacc[nt][1] - mn0); rs0 += sacc[nt][1];
            sacc[nt][2] = __expf(sacc[nt][2] - mn1); rs1 += sacc[nt][2];
            sacc[nt][3] = __expf(sacc[nt][3] - mn1); rs1 += sacc[nt][3];
        }
        rs0 += __shfl_xor_sync(0xffffffffu, rs0, 1);
        rs0 += __shfl_xor_sync(0xffffffffu, rs0, 2);
        rs1 += __shfl_xor_sync(0xffffffffu, rs1, 1);
        rs1 += __shfl_xor_sync(0xffffffffu, rs1, 2);
        lsum[0] = lsum[0] * fac0 + rs0;
        lsum[1] = lsum[1] * fac1 + rs1;

#pragma unroll
        for (int dt = 0; dt < 16; dt++) {
            oacc[dt][0] *= fac0; oacc[dt][1] *= fac0;
            oacc[dt][2] *= fac1; oacc[dt][3] *= fac1;
        }

        // Convert P to tf32 bits in place (float-typed registers carry bits)
#pragma unroll
        for (int nt = 0; nt < 16; nt++)
#pragma unroll
            for (int e = 0; e < 4; e++)
                sacc[nt][e] = __uint_as_float(f2tf32(sacc[nt][e]));

        // ---- O += P V : reshape P fragment via quad shuffles ----
        const int lbase = lane & ~3;
        const int src0  = lbase + (tig >> 1);
        const bool odd  = tig & 1;
#pragma unroll
        for (int c = 0; c < 16; c++) {
            float e0 = __shfl_sync(0xffffffffu, sacc[c][0], src0);
            float e1 = __shfl_sync(0xffffffffu, sacc[c][1], src0);
            float g0 = __shfl_sync(0xffffffffu, sacc[c][2], src0);
            float g1 = __shfl_sync(0xffffffffu, sacc[c][3], src0);
            float f0 = __shfl_sync(0xffffffffu, sacc[c][0], src0 + 2);
            float f1 = __shfl_sync(0xffffffffu, sacc[c][1], src0 + 2);
            float h0 = __shfl_sync(0xffffffffu, sacc[c][2], src0 + 2);
            float h1 = __shfl_sync(0xffffffffu, sacc[c][3], src0 + 2);
            unsigned a[4];
            a[0] = __float_as_uint(odd ? e1 : e0);   // P[gid  ][8c+tig]
            a[1] = __float_as_uint(odd ? g1 : g0);   // P[gid+8][8c+tig]
            a[2] = __float_as_uint(odd ? f1 : f0);   // P[gid  ][8c+tig+4]
            a[3] = __float_as_uint(odd ? h1 : h0);   // P[gid+8][8c+tig+4]
            const unsigned* V0 = Vs + (8 * c + tig) * FL_STRIDE;
            const unsigned* V1 = V0 + 4 * FL_STRIDE;
#pragma unroll
            for (int dt = 0; dt < 16; dt++) {
                int dc = dt * 8 + gid;
                mma_tf32(oacc[dt], a, V0[dc], V1[dc]);
            }
        }
    }

    // ---- epilogue: normalize + write to (B,L,D) ----
    const float inv0 = 1.0f / lsum[0];
    const float inv1 = 1.0f / lsum[1];
    const int r0 = q0 + wq + gid;
    const int r1 = r0 + 8;
#pragma unroll
    for (int dt = 0; dt < 16; dt++) {
        int col = h * DH + dt * 8 + 2 * tig;
        *(float2*)(g_y + (size_t)(b * L_ + r0) * D_ + col) =
            make_float2(oacc[dt][0] * inv0, oacc[dt][1] * inv0);
        *(float2*)(g_y + (size_t)(b * L_ + r1) * D_ + col) =
            make_float2(oacc[dt][2] * inv1, oacc[dt][3] * inv1);
    }
}

// ---------------------------------------------------------------------------
// Launcher
// ---------------------------------------------------------------------------
extern "C" void kernel_launch(void* const* d_in, const int* in_sizes, int n_in,
                              void* d_out, int out_size) {
    const float* x     = nullptr;
    const int*   am    = nullptr;
    const float* wqkv  = nullptr;
    const float* wproj = nullptr;

    for (int i = 0; i < n_in; i++) {
        switch (in_sizes[i]) {
            case BL * D_:      x     = (const float*)d_in[i]; break;
            case BL:           am    = (const int*)d_in[i];   break;
            case D_ * 3 * D_:  wqkv  = (const float*)d_in[i]; break;
            case D_ * D_:      wproj = (const float*)d_in[i]; break;
            default: break;
        }
    }
    if (!x)     x     = (const float*)d_in[0];
    if (!am)    am    = (const int*)d_in[1];
    if (!wqkv)  wqkv  = (const float*)d_in[2];
    if (!wproj) wproj = (const float*)d_in[3];

    float* qkv_p; cudaGetSymbolAddress((void**)&qkv_p, g_qkv);
    float* y_p;   cudaGetSymbolAddress((void**)&y_p,   g_y);

    cudaFuncSetAttribute(flash_tf32_kernel,
                         cudaFuncAttributeMaxDynamicSharedMemorySize,
                         SMEM_FLASH_BYTES);

    // K0: RoPE tables
    rope_tables_kernel<<<(L_ * 64 + 255) / 256, 256>>>();

    // K1: qkv = x @ w_qkv   (4096 x 6144 x 2048)
    sgemm_tf32_kernel<<<dim3(3 * D_ / 128, BL / 128), 256>>>(x, wqkv, qkv_p,
                                                             BL, 3 * D_, D_);

    // K2: RoPE + split into (B,H,L,Dh)
    rope_split_kernel<<<BL, 256>>>();

    // K3: causal flash attention (tf32 tensor cores) -> g_y (B,L,D)
    flash_tf32_kernel<<<dim3(L_ / 128, B_ * H_), 256, SMEM_FLASH_BYTES>>>(am);

    // K4: out = y @ w_proj   (4096 x 2048 x 2048)
    sgemm_tf32_kernel<<<dim3(D_ / 128, BL / 128), 256>>>(y_p, wproj, (float*)d_out,
                                                         BL, D_, D_);
}

// round 10
// speedup vs baseline: 2.6868x; 1.0221x over previous
#include <cuda_runtime.h>
#include <math.h>

// Problem constants
#define B_  2
#define L_  2048
#define D_  2048
#define H_  16
#define DH  128
#define BL  (B_ * L_)          // 4096
#define NEG (-1.0e9f)

// ---------------------------------------------------------------------------
// Scratch (device globals; no runtime allocation allowed)
// ---------------------------------------------------------------------------
__device__ float    g_qkv[(size_t)BL * 3 * D_];
__device__ unsigned g_q[(size_t)B_ * H_ * L_ * DH];   // tf32 bits
__device__ unsigned g_k[(size_t)B_ * H_ * L_ * DH];   // tf32 bits
__device__ unsigned g_v[(size_t)B_ * H_ * L_ * DH];   // tf32 bits
__device__ float    g_y[(size_t)BL * D_];
__device__ float    g_cos[L_ * 64];
__device__ float    g_sin[L_ * 64];

// ---------------------------------------------------------------------------
// K0: RoPE tables.
// ---------------------------------------------------------------------------
__global__ void rope_tables_kernel() {
    int idx = blockIdx.x * blockDim.x + threadIdx.x;
    if (idx >= L_ * 64) return;
    int l = idx >> 6;
    int i = idx & 63;
    float invf = (float)exp(-((double)i / 64.0) * log(10000.0));
    float arg  = (float)l * invf;                 // fp32 multiply like reference
    g_cos[idx] = (float)cos((double)arg);
    g_sin[idx] = (float)sin((double)arg);
}

// ---------------------------------------------------------------------------
// tf32 / async helpers
// ---------------------------------------------------------------------------
__device__ __forceinline__ unsigned f2tf32(float x) {
    unsigned r;
    asm("cvt.rna.tf32.f32 %0, %1;" : "=r"(r) : "f"(x));
    return r;
}

__device__ __forceinline__ void mma_tf32(float (&d)[4], const unsigned (&a)[4],
                                         unsigned b0, unsigned b1) {
    asm volatile(
        "mma.sync.aligned.m16n8k8.row.col.f32.tf32.tf32.f32 "
        "{%0,%1,%2,%3}, {%4,%5,%6,%7}, {%8,%9}, {%0,%1,%2,%3};\n"
        : "+f"(d[0]), "+f"(d[1]), "+f"(d[2]), "+f"(d[3])
        : "r"(a[0]), "r"(a[1]), "r"(a[2]), "r"(a[3]), "r"(b0), "r"(b1));
}

__device__ __forceinline__ unsigned smem_u32(const void* p) {
    return (unsigned)__cvta_generic_to_shared(p);
}

__device__ __forceinline__ void cp_async16(unsigned dst, const void* src) {
    asm volatile("cp.async.cg.shared.global [%0], [%1], 16;\n"
                 :: "r"(dst), "l"(src));
}

__device__ __forceinline__ void cp_async_commit() {
    asm volatile("cp.async.commit_group;\n");
}

__device__ __forceinline__ void cp_async_wait_all() {
    asm volatile("cp.async.wait_group 0;\n");
}

// ---------------------------------------------------------------------------
// K1/K4: tf32 GEMM, cp.async double-buffered, 2 CTAs/SM.
// C[M,N] = A[M,K]*B[K,N], row-major. 128x128 tile, BK=32, 256 thr, 2x4 warps.
// Smem holds raw fp32: A row-major stride 36, B stride 132 (both give
// conflict-free fragment LDS: bank = 4*gid + tig). cvt to tf32 at frag load.
// ---------------------------------------------------------------------------
#define AS_STRIDE 36
#define BS_STRIDE 132
#define GEMM_STAGE_FLOATS (128 * AS_STRIDE + 32 * BS_STRIDE)   // 8832
#define GEMM_SMEM_BYTES   (2 * GEMM_STAGE_FLOATS * 4)          // 70656

__device__ __forceinline__ void gemm_issue_loads(
    float* Ab, float* Bb, const float* __restrict__ A,
    const float* __restrict__ Bm, int K, int N, int m0, int n0, int k0, int tid) {
#pragma unroll
    for (int it = 0; it < 4; it++) {
        int fid = tid + it * 256;
        int ra  = fid >> 3, ca = fid & 7;
        cp_async16(smem_u32(Ab + ra * AS_STRIDE + ca * 4),
                   A + (size_t)(m0 + ra) * K + k0 + ca * 4);
        int rb  = fid >> 5, cb = fid & 31;
        cp_async16(smem_u32(Bb + rb * BS_STRIDE + cb * 4),
                   Bm + (size_t)(k0 + rb) * N + n0 + cb * 4);
    }
    cp_async_commit();
}

__global__ __launch_bounds__(256, 2)
void sgemm_tf32_kernel(const float* __restrict__ A, const float* __restrict__ Bm,
                       float* __restrict__ C, int M, int N, int K) {
    extern __shared__ float gsm[];
    float* Abuf[2] = { gsm, gsm + GEMM_STAGE_FLOATS };
    float* Bbuf[2] = { gsm + 128 * AS_STRIDE,
                       gsm + GEMM_STAGE_FLOATS + 128 * AS_STRIDE };

    const int tid  = threadIdx.x;
    const int lane = tid & 31;
    const int w    = tid >> 5;
    const int gid  = lane >> 2;
    const int tig  = lane & 3;
    const int wm   = (w >> 2) * 64;
    const int wn   = (w & 3) * 32;
    const int m0   = blockIdx.y * 128;
    const int n0   = blockIdx.x * 128;

    float acc[4][4][4];
#pragma unroll
    for (int mt = 0; mt < 4; mt++)
#pragma unroll
        for (int nt = 0; nt < 4; nt++)
#pragma unroll
            for (int i = 0; i < 4; i++) acc[mt][nt][i] = 0.0f;

    gemm_issue_loads(Abuf[0], Bbuf[0], A, Bm, K, N, m0, n0, 0, tid);

    const int ntiles = K / 32;
    for (int t = 0; t < ntiles; t++) {
        const int cur = t & 1;
        cp_async_wait_all();
        __syncthreads();   // cur data visible; all warps done with buf cur^1

        if (t + 1 < ntiles)
            gemm_issue_loads(Abuf[cur ^ 1], Bbuf[cur ^ 1], A, Bm, K, N,
                             m0, n0, (t + 1) * 32, tid);

        const float* As = Abuf[cur];
        const float* Bs = Bbuf[cur];
#pragma unroll
        for (int kk = 0; kk < 32; kk += 8) {
            unsigned af[4][4], bf[4][2];
#pragma unroll
            for (int mt = 0; mt < 4; mt++) {
                const float* ar0 = As + (wm + mt * 16 + gid) * AS_STRIDE + kk + tig;
                const float* ar1 = ar0 + 8 * AS_STRIDE;
                af[mt][0] = f2tf32(ar0[0]);
                af[mt][1] = f2tf32(ar1[0]);
                af[mt][2] = f2tf32(ar0[4]);
                af[mt][3] = f2tf32(ar1[4]);
            }
#pragma unroll
            for (int nt = 0; nt < 4; nt++) {
                int nb = wn + nt * 8 + gid;
                bf[nt][0] = f2tf32(Bs[(kk + tig) * BS_STRIDE + nb]);
                bf[nt][1] = f2tf32(Bs[(kk + tig + 4) * BS_STRIDE + nb]);
            }
#pragma unroll
            for (int mt = 0; mt < 4; mt++)
#pragma unroll
                for (int nt = 0; nt < 4; nt++)
                    mma_tf32(acc[mt][nt], af[mt], bf[nt][0], bf[nt][1]);
        }
    }

    // Epilogue
#pragma unroll
    for (int mt = 0; mt < 4; mt++) {
#pragma unroll
        for (int nt = 0; nt < 4; nt++) {
            int r = m0 + wm + mt * 16 + gid;
            int c = n0 + wn + nt * 8 + tig * 2;
            float* p0 = C + (size_t)r * N + c;
            *(float2*)p0 = make_float2(acc[mt][nt][0], acc[mt][nt][1]);
            float* p1 = p0 + (size_t)8 * N;
            *(float2*)p1 = make_float2(acc[mt][nt][2], acc[mt][nt][3]);
        }
    }
}

// ---------------------------------------------------------------------------
// K2: split qkv, RoPE q,k, scatter into (B,H,L,Dh) as tf32 bits.
// ---------------------------------------------------------------------------
__global__ __launch_bounds__(256)
void rope_split_kernel() {
    const int row = blockIdx.x;
    const int b = row / L_;
    const int l = row - b * L_;
    const float* src = g_qkv + (size_t)row * 3 * D_;

    for (int d = threadIdx.x; d < D_; d += blockDim.x) {
        int h  = d >> 7;
        int dd = d & 127;
        int fi = dd & 63;
        float c = g_cos[l * 64 + fi];
        float s = g_sin[l * 64 + fi];
        size_t dst = (((size_t)(b * H_ + h)) * L_ + l) * DH + dd;

        float qv   = src[d];
        float qrot = (dd < 64) ? -src[d + 64] : src[d - 64];
        g_q[dst] = f2tf32(qv * c + qrot * s);

        float kv   = src[D_ + d];
        float krot = (dd < 64) ? -src[D_ + d + 64] : src[D_ + d - 64];
        g_k[dst] = f2tf32(kv * c + krot * s);

        g_v[dst] = f2tf32(src[2 * D_ + d]);
    }
}

// ---------------------------------------------------------------------------
// K3: causal flash attention on tf32 tensor cores (preconverted operands).
// ---------------------------------------------------------------------------
#define FL_STRIDE 136
#define SMEM_FLASH_BYTES (3 * 128 * FL_STRIDE * 4 + 512)

__global__ __launch_bounds__(256)
void flash_tf32_kernel(const int* __restrict__ amask) {
    extern __shared__ unsigned smu[];
    unsigned* Qs = smu;                          // [q][d]
    unsigned* Ks = smu + 128 * FL_STRIDE;        // [d][k^swz]
    unsigned* Vs = smu + 2 * 128 * FL_STRIDE;    // [k][d]
    int* msk = (int*)(smu + 3 * 128 * FL_STRIDE);

    const int tid  = threadIdx.x;
    const int lane = tid & 31;
    const int w    = tid >> 5;
    const int gid  = lane >> 2;
    const int tig  = lane & 3;
    const int qt   = (int)gridDim.x - 1 - blockIdx.x;  // heavy tiles first
    const int bh   = blockIdx.y;
    const int b    = bh >> 4;
    const int h    = bh & 15;
    const int q0   = qt * 128;
    const int wq   = w * 16;

    const unsigned* Qg = g_q + ((size_t)bh * L_ + q0) * DH;
    const unsigned* Kg = g_k + (size_t)bh * L_ * DH;
    const unsigned* Vg = g_v + (size_t)bh * L_ * DH;

    // Load Q tile (already tf32 bits)
#pragma unroll
    for (int it = 0; it < 16; it++) {
        int idx = tid + it * 256;
        int r   = idx >> 5;
        int c4  = idx & 31;
        *(uint4*)(&Qs[r * FL_STRIDE + c4 * 4]) =
            *(const uint4*)(Qg + (size_t)r * DH + c4 * 4);
    }

    float oacc[16][4];
    float mprev[2], lsum[2];
#pragma unroll
    for (int dt = 0; dt < 16; dt++)
#pragma unroll
        for (int e = 0; e < 4; e++) oacc[dt][e] = 0.0f;
    mprev[0] = mprev[1] = -INFINITY;
    lsum[0] = lsum[1] = 0.0f;

    const float scale = 0.088388347648318447f;   // 1/sqrt(128)
    const int rowa0 = (wq + gid) * FL_STRIDE;
    const int rowa1 = rowa0 + 8 * FL_STRIDE;

    for (int kt = 0; kt <= qt; kt++) {
        const int k0 = kt * 128;
        __syncthreads();   // all warps done reading Ks/Vs from prev iter

        // V tile via cp.async (16B), K tile transposed+swizzled via LDG/STS
#pragma unroll
        for (int it = 0; it < 16; it++) {
            int idx = tid + it * 256;
            int r   = idx >> 5;
            int c4  = idx & 31;
            cp_async16(smem_u32(&Vs[r * FL_STRIDE + c4 * 4]),
                       Vg + (size_t)(k0 + r) * DH + c4 * 4);
        }
        cp_async_commit();
#pragma unroll
        for (int it = 0; it < 16; it++) {
            int idx = tid + it * 256;
            int r   = idx >> 5;
            int c4  = idx & 31;
            uint4 kv = *(const uint4*)(Kg + (size_t)(k0 + r) * DH + c4 * 4);
            int d0 = c4 * 4;
            Ks[(d0 + 0) * FL_STRIDE + (r ^ ((d0 + 0) >> 2))] = kv.x;
            Ks[(d0 + 1) * FL_STRIDE + (r ^ ((d0 + 1) >> 2))] = kv.y;
            Ks[(d0 + 2) * FL_STRIDE + (r ^ ((d0 + 2) >> 2))] = kv.z;
            Ks[(d0 + 3) * FL_STRIDE + (r ^ ((d0 + 3) >> 2))] = kv.w;
        }
        if (tid < 128) msk[tid] = amask[b * L_ + k0 + tid];
        cp_async_wait_all();
        __syncthreads();

        // ---- S = Q K^T ----
        float sacc[16][4];
#pragma unroll
        for (int nt = 0; nt < 16; nt++)
#pragma unroll
            for (int e = 0; e < 4; e++) sacc[nt][e] = 0.0f;

#pragma unroll
        for (int kk = 0; kk < 128; kk += 8) {
            unsigned a[4];
            a[0] = Qs[rowa0 + kk + tig];
            a[1] = Qs[rowa1 + kk + tig];
            a[2] = Qs[rowa0 + kk + tig + 4];
            a[3] = Qs[rowa1 + kk + tig + 4];
            const int d0 = kk + tig, d1 = d0 + 4;
            const unsigned* K0 = Ks + d0 * FL_STRIDE;
            const unsigned* K1 = Ks + d1 * FL_STRIDE;
            const int sw0 = d0 >> 2, sw1 = d1 >> 2;
#pragma unroll
            for (int nt = 0; nt < 16; nt++) {
                int kc = nt * 8 + gid;
                mma_tf32(sacc[nt], a, K0[kc ^ sw0], K1[kc ^ sw1]);
            }
        }

        // ---- scale + mask ----
        const bool diag = (kt == qt);
        const int qi0 = q0 + wq + gid;
        const int qi1 = qi0 + 8;
#pragma unroll
        for (int nt = 0; nt < 16; nt++) {
            int kjb = nt * 8 + 2 * tig;
#pragma unroll
            for (int e = 0; e < 4; e++) {
                int kj = kjb + (e & 1);
                int qi = (e < 2) ? qi0 : qi1;
                float v = sacc[nt][e] * scale;
                if ((diag && (k0 + kj) > qi) || (msk[kj] == 0)) v = NEG;
                sacc[nt][e] = v;
            }
        }

        // ---- online softmax (warp-local rows) ----
        float mx0 = -INFINITY, mx1 = -INFINITY;
#pragma unroll
        for (int nt = 0; nt < 16; nt++) {
            mx0 = fmaxf(mx0, fmaxf(sacc[nt][0], sacc[nt][1]));
            mx1 = fmaxf(mx1, fmaxf(sacc[nt][2], sacc[nt][3]));
        }
        mx0 = fmaxf(mx0, __shfl_xor_sync(0xffffffffu, mx0, 1));
        mx0 = fmaxf(mx0, __shfl_xor_sync(0xffffffffu, mx0, 2));
        mx1 = fmaxf(mx1, __shfl_xor_sync(0xffffffffu, mx1, 1));
        mx1 = fmaxf(mx1, __shfl_xor_sync(0xffffffffu, mx1, 2));

        float mn0 = fmaxf(mprev[0], mx0);
        float mn1 = fmaxf(mprev[1], mx1);
        float fac0 = __expf(mprev[0] - mn0);
        float fac1 = __expf(mprev[1] - mn1);
        mprev[0] = mn0; mprev[1] = mn1;

        float rs0 = 0.0f, rs1 = 0.0f;
#pragma unroll
        for (int nt = 0; nt < 16; nt++) {
            sacc[nt][0] = __expf(sacc[nt][0] - mn0); rs0 += sacc[nt][0];
            sacc[nt][1] = __expf(sacc[nt][1] - mn0); rs0 += sacc[nt][1];
            sacc[nt][2] = __expf(sacc[nt][2] - mn1); rs1 += sacc[nt][2];
            sacc[nt][3] = __expf(sacc[nt][3] - mn1); rs1 += sacc[nt][3];
        }
        rs0 += __shfl_xor_sync(0xffffffffu, rs0, 1);
        rs0 += __shfl_xor_sync(0xffffffffu, rs0, 2);
        rs1 += __shfl_xor_sync(0xffffffffu, rs1, 1);
        rs1 += __shfl_xor_sync(0xffffffffu, rs1, 2);
        lsum[0] = lsum[0] * fac0 + rs0;
        lsum[1] = lsum[1] * fac1 + rs1;

#pragma unroll
        for (int dt = 0; dt < 16; dt++) {
            oacc[dt][0] *= fac0; oacc[dt][1] *= fac0;
            oacc[dt][2] *= fac1; oacc[dt][3] *= fac1;
        }

        // P -> tf32 bits in place
#pragma unroll
        for (int nt = 0; nt < 16; nt++)
#pragma unroll
            for (int e = 0; e < 4; e++)
                sacc[nt][e] = __uint_as_float(f2tf32(sacc[nt][e]));

        // ---- O += P V ----
        const int lbase = lane & ~3;
        const int src0  = lbase + (tig >> 1);
        const bool odd  = tig & 1;
#pragma unroll
        for (int c = 0; c < 16; c++) {
            float e0 = __shfl_sync(0xffffffffu, sacc[c][0], src0);
            float e1 = __shfl_sync(0xffffffffu, sacc[c][1], src0);
            float g0 = __shfl_sync(0xffffffffu, sacc[c][2], src0);
            float g1 = __shfl_sync(0xffffffffu, sacc[c][3], src0);
            float f0 = __shfl_sync(0xffffffffu, sacc[c][0], src0 + 2);
            float f1 = __shfl_sync(0xffffffffu, sacc[c][1], src0 + 2);
            float h0 = __shfl_sync(0xffffffffu, sacc[c][2], src0 + 2);
            float h1 = __shfl_sync(0xffffffffu, sacc[c][3], src0 + 2);
            unsigned a[4];
            a[0] = __float_as_uint(odd ? e1 : e0);
            a[1] = __float_as_uint(odd ? g1 : g0);
            a[2] = __float_as_uint(odd ? f1 : f0);
            a[3] = __float_as_uint(odd ? h1 : h0);
            const unsigned* V0 = Vs + (8 * c + tig) * FL_STRIDE;
            const unsigned* V1 = V0 + 4 * FL_STRIDE;
#pragma unroll
            for (int dt = 0; dt < 16; dt++) {
                int dc = dt * 8 + gid;
                mma_tf32(oacc[dt], a, V0[dc], V1[dc]);
            }
        }
    }

    // ---- epilogue ----
    const float inv0 = 1.0f / lsum[0];
    const float inv1 = 1.0f / lsum[1];
    const int r0 = q0 + wq + gid;
    const int r1 = r0 + 8;
#pragma unroll
    for (int dt = 0; dt < 16; dt++) {
        int col = h * DH + dt * 8 + 2 * tig;
        *(float2*)(g_y + (size_t)(b * L_ + r0) * D_ + col) =
            make_float2(oacc[dt][0] * inv0, oacc[dt][1] * inv0);
        *(float2*)(g_y + (size_t)(b * L_ + r1) * D_ + col) =
            make_float2(oacc[dt][2] * inv1, oacc[dt][3] * inv1);
    }
}

// ---------------------------------------------------------------------------
// Launcher
// ---------------------------------------------------------------------------
extern "C" void kernel_launch(void* const* d_in, const int* in_sizes, int n_in,
                              void* d_out, int out_size) {
    const float* x     = nullptr;
    const int*   am    = nullptr;
    const float* wqkv  = nullptr;
    const float* wproj = nullptr;

    for (int i = 0; i < n_in; i++) {
        switch (in_sizes[i]) {
            case BL * D_:      x     = (const float*)d_in[i]; break;
            case BL:           am    = (const int*)d_in[i];   break;
            case D_ * 3 * D_:  wqkv  = (const float*)d_in[i]; break;
            case D_ * D_:      wproj = (const float*)d_in[i]; break;
            default: break;
        }
    }
    if (!x)     x     = (const float*)d_in[0];
    if (!am)    am    = (const int*)d_in[1];
    if (!wqkv)  wqkv  = (const float*)d_in[2];
    if (!wproj) wproj = (const float*)d_in[3];

    float* qkv_p; cudaGetSymbolAddress((void**)&qkv_p, g_qkv);
    float* y_p;   cudaGetSymbolAddress((void**)&y_p,   g_y);

    cudaFuncSetAttribute(flash_tf32_kernel,
                         cudaFuncAttributeMaxDynamicSharedMemorySize,
                         SMEM_FLASH_BYTES);
    cudaFuncSetAttribute(sgemm_tf32_kernel,
                         cudaFuncAttributeMaxDynamicSharedMemorySize,
                         GEMM_SMEM_BYTES);

    // K0: RoPE tables
    rope_tables_kernel<<<(L_ * 64 + 255) / 256, 256>>>();

    // K1: qkv = x @ w_qkv   (4096 x 6144 x 2048)
    sgemm_tf32_kernel<<<dim3(3 * D_ / 128, BL / 128), 256, GEMM_SMEM_BYTES>>>(
        x, wqkv, qkv_p, BL, 3 * D_, D_);

    // K2: RoPE + split into (B,H,L,Dh), tf32 bits
    rope_split_kernel<<<BL, 256>>>();

    // K3: causal flash attention (tf32 tensor cores) -> g_y (B,L,D)
    flash_tf32_kernel<<<dim3(L_ / 128, B_ * H_), 256, SMEM_FLASH_BYTES>>>(am);

    // K4: out = y @ w_proj   (4096 x 2048 x 2048)
    sgemm_tf32_kernel<<<dim3(D_ / 128, BL / 128), 256, GEMM_SMEM_BYTES>>>(
        y_p, wproj, (float*)d_out, BL, D_, D_);
}

// round 12
// speedup vs baseline: 6.6621x; 2.4796x over previous
#include <cuda_runtime.h>
#include <cuda_fp16.h>
#include <math.h>

// Problem constants
#define B_  2
#define L_  2048
#define D_  2048
#define H_  16
#define DH  128
#define BL  (B_ * L_)          // 4096
#define NEG (-1.0e9f)

// ---------------------------------------------------------------------------
// Scratch (device globals; no runtime allocation allowed)
// ---------------------------------------------------------------------------
__device__ float  g_qkv[(size_t)BL * 3 * D_];
__device__ __half g_xh[(size_t)BL * D_];
__device__ __half g_wqkvh[(size_t)D_ * 3 * D_];
__device__ __half g_wprojh[(size_t)D_ * D_];
__device__ __half g_q[(size_t)B_ * H_ * L_ * DH];
__device__ __half g_k[(size_t)B_ * H_ * L_ * DH];
__device__ __half g_v[(size_t)B_ * H_ * L_ * DH];
__device__ __half g_y[(size_t)BL * D_];
__device__ float  g_cos[L_ * 64];
__device__ float  g_sin[L_ * 64];

// ---------------------------------------------------------------------------
// K0: RoPE tables.
// ---------------------------------------------------------------------------
__global__ void rope_tables_kernel() {
    int idx = blockIdx.x * blockDim.x + threadIdx.x;
    if (idx >= L_ * 64) return;
    int l = idx >> 6;
    int i = idx & 63;
    float invf = (float)exp(-((double)i / 64.0) * log(10000.0));
    float arg  = (float)l * invf;                 // fp32 multiply like reference
    g_cos[idx] = (float)cos((double)arg);
    g_sin[idx] = (float)sin((double)arg);
}

// ---------------------------------------------------------------------------
// fp32 -> fp16 bulk convert (vectorized)
// ---------------------------------------------------------------------------
__global__ __launch_bounds__(256)
void f2h_kernel(const float* __restrict__ s, __half* __restrict__ d, int n4) {
    int i = blockIdx.x * blockDim.x + threadIdx.x;
    if (i >= n4) return;
    float4 v = ((const float4*)s)[i];
    __half2* o = (__half2*)d + 2 * (size_t)i;
    o[0] = __floats2half2_rn(v.x, v.y);
    o[1] = __floats2half2_rn(v.z, v.w);
}

// ---------------------------------------------------------------------------
// MMA / ldmatrix / async helpers
// ---------------------------------------------------------------------------
__device__ __forceinline__ void mma_f16(float (&d)[4], const unsigned (&a)[4],
                                        unsigned b0, unsigned b1) {
    asm volatile(
        "mma.sync.aligned.m16n8k16.row.col.f32.f16.f16.f32 "
        "{%0,%1,%2,%3}, {%4,%5,%6,%7}, {%8,%9}, {%0,%1,%2,%3};\n"
        : "+f"(d[0]), "+f"(d[1]), "+f"(d[2]), "+f"(d[3])
        : "r"(a[0]), "r"(a[1]), "r"(a[2]), "r"(a[3]), "r"(b0), "r"(b1));
}

__device__ __forceinline__ void ldsm_x4(unsigned addr, unsigned& r0, unsigned& r1,
                                        unsigned& r2, unsigned& r3) {
    asm volatile("ldmatrix.sync.aligned.m8n8.x4.shared.b16 {%0,%1,%2,%3}, [%4];"
                 : "=r"(r0), "=r"(r1), "=r"(r2), "=r"(r3) : "r"(addr));
}

__device__ __forceinline__ void ldsm_x4_t(unsigned addr, unsigned& r0, unsigned& r1,
                                          unsigned& r2, unsigned& r3) {
    asm volatile("ldmatrix.sync.aligned.m8n8.x4.trans.shared.b16 {%0,%1,%2,%3}, [%4];"
                 : "=r"(r0), "=r"(r1), "=r"(r2), "=r"(r3) : "r"(addr));
}

__device__ __forceinline__ unsigned smem_u32(const void* p) {
    return (unsigned)__cvta_generic_to_shared(p);
}

__device__ __forceinline__ void cp_async16(unsigned dst, const void* src) {
    asm volatile("cp.async.cg.shared.global [%0], [%1], 16;\n"
                 :: "r"(dst), "l"(src));
}

__device__ __forceinline__ void cp_async_commit() {
    asm volatile("cp.async.commit_group;\n");
}

__device__ __forceinline__ void cp_async_wait_all() {
    asm volatile("cp.async.wait_group 0;\n");
}

__device__ __forceinline__ unsigned h2u(__half2 h) {
    return *(unsigned*)&h;
}

// ---------------------------------------------------------------------------
// K1/K4: fp16 GEMM (m16n8k16), cp.async double-buffered, 2 CTAs/SM.
// C[M,N] = A[M,K]*B[K,N] with A,B fp16 row-major, C fp32.
// 128x128 tile, BK=32, 256 thr (8 warps 2x4, 64x32 warp tile).
// As [m][k] stride 40 halves; Bs [k][n] stride 136 halves.
// Fragments via ldmatrix (A) / ldmatrix.trans (B); all phases conflict-free.
// ---------------------------------------------------------------------------
#define AS_H 40
#define BS_H 136
#define GEMM_STAGE_HALVES (128 * AS_H + 32 * BS_H)   // 9472
#define GEMM_SMEM_BYTES   (2 * GEMM_STAGE_HALVES * 2)

__device__ __forceinline__ void hgemm_issue(
    __half* Ab, __half* Bb, const __half* __restrict__ A,
    const __half* __restrict__ Bm, int K, int N, int m0, int n0, int k0, int tid) {
#pragma unroll
    for (int it = 0; it < 2; it++) {
        int ca = tid + it * 256;             // 512 chunks of 8 halves (A)
        cp_async16(smem_u32(Ab + (ca >> 2) * AS_H + (ca & 3) * 8),
                   A + (size_t)(m0 + (ca >> 2)) * K + k0 + (ca & 3) * 8);
        int cb = tid + it * 256;             // 512 chunks (B)
        cp_async16(smem_u32(Bb + (cb >> 4) * BS_H + (cb & 15) * 8),
                   Bm + (size_t)(k0 + (cb >> 4)) * N + n0 + (cb & 15) * 8);
    }
    cp_async_commit();
}

__global__ __launch_bounds__(256, 2)
void hgemm_kernel(const __half* __restrict__ A, const __half* __restrict__ Bm,
                  float* __restrict__ C, int M, int N, int K) {
    extern __shared__ __half hsm[];
    __half* Abuf[2] = { hsm, hsm + GEMM_STAGE_HALVES };
    __half* Bbuf[2] = { hsm + 128 * AS_H, hsm + GEMM_STAGE_HALVES + 128 * AS_H };

    const int tid  = threadIdx.x;
    const int lane = tid & 31;
    const int w    = tid >> 5;
    const int gid  = lane >> 2;
    const int tig  = lane & 3;
    const int l7   = lane & 7;
    const int lg   = lane >> 3;          // 0..3 (ldmatrix group)
    const int wm   = (w >> 2) * 64;
    const int wn   = (w & 3) * 32;
    const int m0   = blockIdx.y * 128;
    const int n0   = blockIdx.x * 128;

    float acc[4][4][4];
#pragma unroll
    for (int mt = 0; mt < 4; mt++)
#pragma unroll
        for (int nt = 0; nt < 4; nt++)
#pragma unroll
            for (int i = 0; i < 4; i++) acc[mt][nt][i] = 0.0f;

    hgemm_issue(Abuf[0], Bbuf[0], A, Bm, K, N, m0, n0, 0, tid);

    // Per-thread ldmatrix row/col components
    const int a_row = l7 + ((lg & 1) << 3);       // + mt*16 + wm
    const int a_col = (lg >> 1) << 3;             // + kk
    const int b_row = l7 + ((lg & 1) << 3);       // + kk
    const int b_col = wn + ((lg >> 1) << 3);      // + ntp*16

    const int ntiles = K / 32;
    for (int t = 0; t < ntiles; t++) {
        const int cur = t & 1;
        cp_async_wait_all();
        __syncthreads();

        if (t + 1 < ntiles)
            hgemm_issue(Abuf[cur ^ 1], Bbuf[cur ^ 1], A, Bm, K, N,
                        m0, n0, (t + 1) * 32, tid);

        const __half* As = Abuf[cur];
        const __half* Bs = Bbuf[cur];
#pragma unroll
        for (int kk = 0; kk < 32; kk += 16) {
            unsigned af[4][4];
#pragma unroll
            for (int mt = 0; mt < 4; mt++) {
                unsigned addr = smem_u32(As + (wm + mt * 16 + a_row) * AS_H + kk + a_col);
                ldsm_x4(addr, af[mt][0], af[mt][1], af[mt][2], af[mt][3]);
            }
#pragma unroll
            for (int ntp = 0; ntp < 2; ntp++) {
                unsigned b0, b1, b2, b3;
                unsigned addr = smem_u32(Bs + (kk + b_row) * BS_H + b_col + ntp * 16);
                ldsm_x4_t(addr, b0, b1, b2, b3);
#pragma unroll
                for (int mt = 0; mt < 4; mt++) {
                    mma_f16(acc[mt][2 * ntp],     af[mt], b0, b1);
                    mma_f16(acc[mt][2 * ntp + 1], af[mt], b2, b3);
                }
            }
        }
    }

    // Epilogue (fp32 out)
#pragma unroll
    for (int mt = 0; mt < 4; mt++) {
#pragma unroll
        for (int nt = 0; nt < 4; nt++) {
            int r = m0 + wm + mt * 16 + gid;
            int c = n0 + wn + nt * 8 + tig * 2;
            float* p0 = C + (size_t)r * N + c;
            *(float2*)p0 = make_float2(acc[mt][nt][0], acc[mt][nt][1]);
            float* p1 = p0 + (size_t)8 * N;
            *(float2*)p1 = make_float2(acc[mt][nt][2], acc[mt][nt][3]);
        }
    }
}

// ---------------------------------------------------------------------------
// K2: split qkv, RoPE q,k, scatter into (B,H,L,Dh) as fp16.
// ---------------------------------------------------------------------------
__global__ __launch_bounds__(256)
void rope_split_kernel() {
    const int row = blockIdx.x;
    const int b = row / L_;
    const int l = row - b * L_;
    const float* src = g_qkv + (size_t)row * 3 * D_;

    for (int d = threadIdx.x; d < D_; d += blockDim.x) {
        int h  = d >> 7;
        int dd = d & 127;
        int fi = dd & 63;
        float c = g_cos[l * 64 + fi];
        float s = g_sin[l * 64 + fi];
        size_t dst = (((size_t)(b * H_ + h)) * L_ + l) * DH + dd;

        float qv   = src[d];
        float qrot = (dd < 64) ? -src[d + 64] : src[d - 64];
        g_q[dst] = __float2half_rn(qv * c + qrot * s);

        float kv   = src[D_ + d];
        float krot = (dd < 64) ? -src[D_ + d + 64] : src[D_ + d - 64];
        g_k[dst] = __float2half_rn(kv * c + krot * s);

        g_v[dst] = __float2half_rn(src[2 * D_ + d]);
    }
}

// ---------------------------------------------------------------------------
// K3: causal flash attention, fp16 m16n8k16.
// 8 warps; warp w owns q rows [w*16, w*16+16) x all 128 k-cols (softmax
// warp-local). Q/K/V all stored [row][d or k] stride 136 halves; K fragments
// via non-trans ldmatrix, V via ldmatrix.trans (no transposes, no swizzles).
// P->A fragment is a pure register pairwise pack (no shuffles).
// ---------------------------------------------------------------------------
#define FLH 136
#define SMEM_FLASH_BYTES (3 * 128 * FLH * 2 + 512)

__global__ __launch_bounds__(256)
void flash_f16_kernel(const int* __restrict__ amask) {
    extern __shared__ __half fsm[];
    __half* Qs = fsm;                      // [q][d]
    __half* Ks = fsm + 128 * FLH;          // [k][d]
    __half* Vs = fsm + 2 * 128 * FLH;      // [k][d]
    int* msk = (int*)(fsm + 3 * 128 * FLH);

    const int tid  = threadIdx.x;
    const int lane = tid & 31;
    const int w    = tid >> 5;
    const int gid  = lane >> 2;
    const int tig  = lane & 3;
    const int l7   = lane & 7;
    const int lg   = lane >> 3;
    const int qt   = (int)gridDim.x - 1 - blockIdx.x;  // heavy tiles first
    const int bh   = blockIdx.y;
    const int b    = bh >> 4;
    const int h    = bh & 15;
    const int q0   = qt * 128;
    const int wq   = w * 16;

    const __half* Qg = g_q + ((size_t)bh * L_ + q0) * DH;
    const __half* Kg = g_k + (size_t)bh * L_ * DH;
    const __half* Vg = g_v + (size_t)bh * L_ * DH;

    // Q tile via cp.async
#pragma unroll
    for (int it = 0; it < 8; it++) {
        int idx = tid + it * 256;            // 2048 chunks of 8 halves
        int r   = idx >> 4;
        int c8  = idx & 15;
        cp_async16(smem_u32(Qs + r * FLH + c8 * 8), Qg + (size_t)r * DH + c8 * 8);
    }
    cp_async_commit();

    float oacc[16][4];
    float mprev[2], lsum[2];
#pragma unroll
    for (int dt = 0; dt < 16; dt++)
#pragma unroll
        for (int e = 0; e < 4; e++) oacc[dt][e] = 0.0f;
    mprev[0] = mprev[1] = -INFINITY;
    lsum[0] = lsum[1] = 0.0f;

    const float scale = 0.088388347648318447f;   // 1/sqrt(128)

    // ldmatrix row/col components
    const int q_row = wq + l7 + ((lg & 1) << 3);  // A (Q): + nothing
    const int q_col = (lg >> 1) << 3;             // + kk
    const int k_row = l7 + ((lg >> 1) << 3);      // B (K): token + n0
    const int k_col = (lg & 1) << 3;              // + kk (d)
    const int v_row = l7 + ((lg & 1) << 3);       // B (V,trans): token + kk
    const int v_col = (lg >> 1) << 3;             // + d0

    for (int kt = 0; kt <= qt; kt++) {
        const int k0 = kt * 128;
        __syncthreads();   // all warps done reading Ks/Vs from prev iter

        // K and V tiles via cp.async
#pragma unroll
        for (int it = 0; it < 8; it++) {
            int idx = tid + it * 256;
            int r   = idx >> 4;
            int c8  = idx & 15;
            cp_async16(smem_u32(Ks + r * FLH + c8 * 8),
                       Kg + (size_t)(k0 + r) * DH + c8 * 8);
            cp_async16(smem_u32(Vs + r * FLH + c8 * 8),
                       Vg + (size_t)(k0 + r) * DH + c8 * 8);
        }
        cp_async_commit();
        if (tid < 128) msk[tid] = amask[b * L_ + k0 + tid];
        cp_async_wait_all();
        __syncthreads();

        // ---- S = Q K^T : 8 d-chunks of 16 ----
        float sacc[16][4];
#pragma unroll
        for (int nt = 0; nt < 16; nt++)
#pragma unroll
            for (int e = 0; e < 4; e++) sacc[nt][e] = 0.0f;

#pragma unroll
        for (int kk = 0; kk < 128; kk += 16) {
            unsigned a[4];
            ldsm_x4(smem_u32(Qs + q_row * FLH + kk + q_col), a[0], a[1], a[2], a[3]);
#pragma unroll
            for (int ntp = 0; ntp < 8; ntp++) {
                unsigned b0, b1, b2, b3;
                ldsm_x4(smem_u32(Ks + (ntp * 16 + k_row) * FLH + kk + k_col),
                        b0, b1, b2, b3);
                mma_f16(sacc[2 * ntp],     a, b0, b1);
                mma_f16(sacc[2 * ntp + 1], a, b2, b3);
            }
        }

        // ---- scale + mask ----
        const bool diag = (kt == qt);
        const int qi0 = q0 + wq + gid;
        const int qi1 = qi0 + 8;
#pragma unroll
        for (int nt = 0; nt < 16; nt++) {
            int kjb = nt * 8 + 2 * tig;
#pragma unroll
            for (int e = 0; e < 4; e++) {
                int kj = kjb + (e & 1);
                int qi = (e < 2) ? qi0 : qi1;
                float v = sacc[nt][e] * scale;
                if ((diag && (k0 + kj) > qi) || (msk[kj] == 0)) v = NEG;
                sacc[nt][e] = v;
            }
        }

        // ---- online softmax (warp-local rows) ----
        float mx0 = -INFINITY, mx1 = -INFINITY;
#pragma unroll
        for (int nt = 0; nt < 16; nt++) {
            mx0 = fmaxf(mx0, fmaxf(sacc[nt][0], sacc[nt][1]));
            mx1 = fmaxf(mx1, fmaxf(sacc[nt][2], sacc[nt][3]));
        }
        mx0 = fmaxf(mx0, __shfl_xor_sync(0xffffffffu, mx0, 1));
        mx0 = fmaxf(mx0, __shfl_xor_sync(0xffffffffu, mx0, 2));
        mx1 = fmaxf(mx1, __shfl_xor_sync(0xffffffffu, mx1, 1));
        mx1 = fmaxf(mx1, __shfl_xor_sync(0xffffffffu, mx1, 2));

        float mn0 = fmaxf(mprev[0], mx0);
        float mn1 = fmaxf(mprev[1], mx1);
        float fac0 = __expf(mprev[0] - mn0);
        float fac1 = __expf(mprev[1] - mn1);
        mprev[0] = mn0; mprev[1] = mn1;

        float rs0 = 0.0f, rs1 = 0.0f;
#pragma unroll
        for (int nt = 0; nt < 16; nt++) {
            sacc[nt][0] = __expf(sacc[nt][0] - mn0); rs0 += sacc[nt][0];
            sacc[nt][1] = __expf(sacc[nt][1] - mn0); rs0 += sacc[nt][1];
            sacc[nt][2] = __expf(sacc[nt][2] - mn1); rs1 += sacc[nt][2];
            sacc[nt][3] = __expf(sacc[nt][3] - mn1); rs1 += sacc[nt][3];
        }
        rs0 += __shfl_xor_sync(0xffffffffu, rs0, 1);
        rs0 += __shfl_xor_sync(0xffffffffu, rs0, 2);
        rs1 += __shfl_xor_sync(0xffffffffu, rs1, 1);
        rs1 += __shfl_xor_sync(0xffffffffu, rs1, 2);
        lsum[0] = lsum[0] * fac0 + rs0;
        lsum[1] = lsum[1] * fac1 + rs1;

#pragma unroll
        for (int dt = 0; dt < 16; dt++) {
            oacc[dt][0] *= fac0; oacc[dt][1] *= fac0;
            oacc[dt][2] *= fac1; oacc[dt][3] *= fac1;
        }

        // ---- O += P V : A fragment = pairwise-packed C fragment ----
#pragma unroll
        for (int c = 0; c < 8; c++) {        // token chunks of 16
            unsigned a[4];
            a[0] = h2u(__floats2half2_rn(sacc[2 * c][0],     sacc[2 * c][1]));
            a[1] = h2u(__floats2half2_rn(sacc[2 * c][2],     sacc[2 * c][3]));
            a[2] = h2u(__floats2half2_rn(sacc[2 * c + 1][0], sacc[2 * c + 1][1]));
            a[3] = h2u(__floats2half2_rn(sacc[2 * c + 1][2], sacc[2 * c + 1][3]));
#pragma unroll
            for (int dtp = 0; dtp < 8; dtp++) {
                unsigned b0, b1, b2, b3;
                ldsm_x4_t(smem_u32(Vs + (c * 16 + v_row) * FLH + dtp * 16 + v_col),
                          b0, b1, b2, b3);
                mma_f16(oacc[2 * dtp],     a, b0, b1);
                mma_f16(oacc[2 * dtp + 1], a, b2, b3);
            }
        }
    }

    // ---- epilogue: normalize, write g_y as fp16 ----
    const float inv0 = 1.0f / lsum[0];
    const float inv1 = 1.0f / lsum[1];
    const int r0 = q0 + wq + gid;
    const int r1 = r0 + 8;
#pragma unroll
    for (int dt = 0; dt < 16; dt++) {
        int col = h * DH + dt * 8 + 2 * tig;
        *(__half2*)(g_y + (size_t)(b * L_ + r0) * D_ + col) =
            __floats2half2_rn(oacc[dt][0] * inv0, oacc[dt][1] * inv0);
        *(__half2*)(g_y + (size_t)(b * L_ + r1) * D_ + col) =
            __floats2half2_rn(oacc[dt][2] * inv1, oacc[dt][3] * inv1);
    }
}

// ---------------------------------------------------------------------------
// Launcher
// ---------------------------------------------------------------------------
extern "C" void kernel_launch(void* const* d_in, const int* in_sizes, int n_in,
                              void* d_out, int out_size) {
    const float* x     = nullptr;
    const int*   am    = nullptr;
    const float* wqkv  = nullptr;
    const float* wproj = nullptr;

    for (int i = 0; i < n_in; i++) {
        switch (in_sizes[i]) {
            case BL * D_:      x     = (const float*)d_in[i]; break;
            case BL:           am    = (const int*)d_in[i];   break;
            case D_ * 3 * D_:  wqkv  = (const float*)d_in[i]; break;
            case D_ * D_:      wproj = (const float*)d_in[i]; break;
            default: break;
        }
    }
    if (!x)     x     = (const float*)d_in[0];
    if (!am)    am    = (const int*)d_in[1];
    if (!wqkv)  wqkv  = (const float*)d_in[2];
    if (!wproj) wproj = (const float*)d_in[3];

    float*  qkv_p;   cudaGetSymbolAddress((void**)&qkv_p,   g_qkv);
    __half* xh_p;    cudaGetSymbolAddress((void**)&xh_p,    g_xh);
    __half* wqkvh_p; cudaGetSymbolAddress((void**)&wqkvh_p, g_wqkvh);
    __half* wprojh_p;cudaGetSymbolAddress((void**)&wprojh_p,g_wprojh);
    __half* y_p;     cudaGetSymbolAddress((void**)&y_p,     g_y);

    cudaFuncSetAttribute(flash_f16_kernel,
                         cudaFuncAttributeMaxDynamicSharedMemorySize,
                         SMEM_FLASH_BYTES);
    cudaFuncSetAttribute(hgemm_kernel,
                         cudaFuncAttributeMaxDynamicSharedMemorySize,
                         GEMM_SMEM_BYTES);

    // K0: RoPE tables + fp16 conversions
    rope_tables_kernel<<<(L_ * 64 + 255) / 256, 256>>>();
    f2h_kernel<<<(BL * D_ / 4 + 255) / 256, 256>>>(x, xh_p, BL * D_ / 4);
    f2h_kernel<<<(D_ * 3 * D_ / 4 + 255) / 256, 256>>>(wqkv, wqkvh_p, D_ * 3 * D_ / 4);
    f2h_kernel<<<(D_ * D_ / 4 + 255) / 256, 256>>>(wproj, wprojh_p, D_ * D_ / 4);

    // K1: qkv = x @ w_qkv   (4096 x 6144 x 2048), fp16 MMA
    hgemm_kernel<<<dim3(3 * D_ / 128, BL / 128), 256, GEMM_SMEM_BYTES>>>(
        xh_p, wqkvh_p, qkv_p, BL, 3 * D_, D_);

    // K2: RoPE + split into (B,H,L,Dh) fp16
    rope_split_kernel<<<BL, 256>>>();

    // K3: causal flash attention (fp16 MMA) -> g_y fp16
    flash_f16_kernel<<<dim3(L_ / 128, B_ * H_), 256, SMEM_FLASH_BYTES>>>(am);

    // K4: out = y @ w_proj   (4096 x 2048 x 2048), fp16 MMA
    hgemm_kernel<<<dim3(D_ / 128, BL / 128), 256, GEMM_SMEM_BYTES>>>(
        y_p, wprojh_p, (float*)d_out, BL, D_, D_);
}